// round 4
// baseline (speedup 1.0000x reference)
#include <cuda_runtime.h>
#include <cuda_bf16.h>
#include <math.h>
#include <float.h>

#define Bb 16
#define Ss 128
#define Tt 128
#define Hh 1024
#define Vv 32000
#define BOSTOK 1

// ---------------- scratch (device globals; no allocs allowed) ----------------
__device__ float g_kproj[Bb * Ss * Hh];                 // 8 MB
__device__ float g_H[(Tt + 1) * Bb * Hh];               // hidden states fp32
__device__ __nv_bfloat16 g_Hbf[Tt * Bb * Hh];           // h_{t+1} rows bf16 (logits A)
__device__ __nv_bfloat16 g_Woutbf[(size_t)Vv * Hh];     // 64 MB bf16 W_out
__device__ __nv_bfloat16 g_embbf[Tt * Bb * Hh];         // gathered dec-in embeddings bf16
__device__ __nv_bfloat16 g_Wihembbf[3 * Hh * Hh];       // Wih[:, :H] bf16
__device__ float g_gxemb[Tt * Bb * 3 * Hh];             // 25 MB emb-part gate preacts (+bih)
// split-precision loop operands
__device__ __nv_bfloat16 g_Wcat_hi[4 * Hh * Hh];        // [Wq; Whh] hi
__device__ __nv_bfloat16 g_Wcat_lo[4 * Hh * Hh];        // [Wq; Whh] lo
__device__ __nv_bfloat16 g_Wc_hi[3 * Hh * Hh];          // Wih[:,H:2H] hi (gate-permuted rows)
__device__ __nv_bfloat16 g_Wc_lo[3 * Hh * Hh];
__device__ __nv_bfloat16 g_hhi[Bb * Hh], g_hlo[Bb * Hh];
__device__ __nv_bfloat16 g_chi[Bb * Hh], g_clo[Bb * Hh];
__device__ float g_q[Bb * Hh];
__device__ float g_gh[Bb * 3 * Hh];
__device__ float g_scores[Bb * Ss];

// ---------------- math helpers ----------------
__device__ __forceinline__ float fast_tanh(float x) {
    float xc = fminf(fmaxf(x, -15.f), 15.f);
    float t = __expf(2.f * xc);
    return __fdividef(t - 1.f, t + 1.f);
}
__device__ __forceinline__ float fast_sigmoid(float x) {
    return __fdividef(1.f, 1.f + __expf(-x));
}
__device__ __forceinline__ uint2 f4_to_bf8(float4 v) {
    __nv_bfloat162 lo = __floats2bfloat162_rn(v.x, v.y);
    __nv_bfloat162 hi = __floats2bfloat162_rn(v.z, v.w);
    uint2 o;
    o.x = *(const unsigned int*)&lo;
    o.y = *(const unsigned int*)&hi;
    return o;
}

// ---------------- fp32 GEMM for kproj ----------------
__global__ __launch_bounds__(256) void gemm_tn_kernel(
    const float* __restrict__ A, const float* __restrict__ Bw, int K)
{
    __shared__ float sA[16][64];
    __shared__ float sB[16][64];
    const int tid = threadIdx.x;
    const int bm = blockIdx.y * 64;
    const int bn = blockIdx.x * 64;
    const int lrow = tid >> 2;
    const int lk = (tid & 3) << 2;
    const int tx = tid & 15;
    const int ty = tid >> 4;

    const float* Ap = A + (size_t)(bm + lrow) * K + lk;
    const float* Bp = Bw + (size_t)(bn + lrow) * K + lk;

    float acc[4][4] = {};
    for (int k0 = 0; k0 < K; k0 += 16) {
        float4 av = *(const float4*)(Ap + k0);
        float4 bv = *(const float4*)(Bp + k0);
        sA[lk + 0][lrow] = av.x; sA[lk + 1][lrow] = av.y;
        sA[lk + 2][lrow] = av.z; sA[lk + 3][lrow] = av.w;
        sB[lk + 0][lrow] = bv.x; sB[lk + 1][lrow] = bv.y;
        sB[lk + 2][lrow] = bv.z; sB[lk + 3][lrow] = bv.w;
        __syncthreads();
#pragma unroll
        for (int kk = 0; kk < 16; kk++) {
            float4 a = *(const float4*)&sA[kk][ty << 2];
            float4 b = *(const float4*)&sB[kk][tx << 2];
            acc[0][0] = fmaf(a.x, b.x, acc[0][0]); acc[0][1] = fmaf(a.x, b.y, acc[0][1]);
            acc[0][2] = fmaf(a.x, b.z, acc[0][2]); acc[0][3] = fmaf(a.x, b.w, acc[0][3]);
            acc[1][0] = fmaf(a.y, b.x, acc[1][0]); acc[1][1] = fmaf(a.y, b.y, acc[1][1]);
            acc[1][2] = fmaf(a.y, b.z, acc[1][2]); acc[1][3] = fmaf(a.y, b.w, acc[1][3]);
            acc[2][0] = fmaf(a.z, b.x, acc[2][0]); acc[2][1] = fmaf(a.z, b.y, acc[2][1]);
            acc[2][2] = fmaf(a.z, b.z, acc[2][2]); acc[2][3] = fmaf(a.z, b.w, acc[2][3]);
            acc[3][0] = fmaf(a.w, b.x, acc[3][0]); acc[3][1] = fmaf(a.w, b.y, acc[3][1]);
            acc[3][2] = fmaf(a.w, b.z, acc[3][2]); acc[3][3] = fmaf(a.w, b.w, acc[3][3]);
        }
        __syncthreads();
    }
#pragma unroll
    for (int i = 0; i < 4; i++) {
        int m = bm + (ty << 2) + i;
        int n = bn + (tx << 2);
        *(float4*)(g_kproj + (size_t)m * Hh + n) =
            make_float4(acc[i][0], acc[i][1], acc[i][2], acc[i][3]);
    }
}

// ---------------- one-time conversions / gathers ----------------
__global__ __launch_bounds__(256) void conv_wout_kernel(const float* __restrict__ W)
{
    size_t n4 = (size_t)Vv * Hh / 4;
    uint2* dst = (uint2*)g_Woutbf;
    const float4* src = (const float4*)W;
    for (size_t i = blockIdx.x * 256 + threadIdx.x; i < n4; i += (size_t)gridDim.x * 256)
        dst[i] = f4_to_bf8(src[i]);
}

__global__ __launch_bounds__(256) void conv_wihemb_kernel(const float* __restrict__ Wih)
{
    int j = blockIdx.x;
    int c = threadIdx.x * 4;
    float4 v = *(const float4*)(Wih + (size_t)j * (2 * Hh) + c);
    *(uint2*)(g_Wihembbf + (size_t)j * Hh + c) = f4_to_bf8(v);
}

// hi/lo split of a float4 -> two uint2 (4 bf16 each)
__device__ __forceinline__ void split_f4(float4 v, uint2* hi, uint2* lo)
{
    __nv_bfloat16 hx = __float2bfloat16(v.x), hy = __float2bfloat16(v.y);
    __nv_bfloat16 hz = __float2bfloat16(v.z), hw = __float2bfloat16(v.w);
    float4 r = make_float4(v.x - __bfloat162float(hx), v.y - __bfloat162float(hy),
                           v.z - __bfloat162float(hz), v.w - __bfloat162float(hw));
    __nv_bfloat162 h01; h01.x = hx; h01.y = hy;
    __nv_bfloat162 h23; h23.x = hz; h23.y = hw;
    uint2 h; h.x = *(unsigned int*)&h01; h.y = *(unsigned int*)&h23;
    *hi = h;
    *lo = f4_to_bf8(r);
}

// [Wq; Whh] -> hi/lo bf16 (rows 0..1023 Wq, 1024..4095 Whh)
__global__ __launch_bounds__(256) void conv_wcat_kernel(
    const float* __restrict__ Wq, const float* __restrict__ Whh)
{
    int r = blockIdx.x;                 // 0..4095
    const float* src = (r < Hh) ? (Wq + (size_t)r * Hh) : (Whh + (size_t)(r - Hh) * Hh);
    int c = threadIdx.x * 4;
    float4 v = *(const float4*)(src + c);
    uint2 hi, lo;
    split_f4(v, &hi, &lo);
    *(uint2*)(g_Wcat_hi + (size_t)r * Hh + c) = hi;
    *(uint2*)(g_Wcat_lo + (size_t)r * Hh + c) = lo;
}

// ctx half of Wih -> hi/lo bf16 with gate-permuted rows: r' = ((j>>3)*3+g)*8 + (j&7)
__global__ __launch_bounds__(256) void conv_wc_kernel(const float* __restrict__ Wih)
{
    int rp = blockIdx.x;                // 0..3071 (permuted)
    int jl = rp & 7;
    int q = rp >> 3;
    int g = q % 3;
    int jg = q / 3;
    int j = jg * 8 + jl;
    const float* src = Wih + (size_t)(g * Hh + j) * (2 * Hh) + Hh;
    int c = threadIdx.x * 4;
    float4 v = *(const float4*)(src + c);
    uint2 hi, lo;
    split_f4(v, &hi, &lo);
    *(uint2*)(g_Wc_hi + (size_t)rp * Hh + c) = hi;
    *(uint2*)(g_Wc_lo + (size_t)rp * Hh + c) = lo;
}

__global__ __launch_bounds__(256) void gather_emb_kernel(
    const float* __restrict__ emb, const int* __restrict__ tgt)
{
    int r = blockIdx.x;
    int t = r >> 4, b = r & 15;
    int tok = (t == 0) ? BOSTOK : tgt[b * Tt + (t - 1)];
    int c = threadIdx.x * 4;
    float4 v = *(const float4*)(emb + (size_t)tok * Hh + c);
    *(uint2*)(g_embbf + (size_t)r * Hh + c) = f4_to_bf8(v);
}

// ---------------- h0 init (fp32 + hi/lo) / hT copy ----------------
__global__ void init_h_kernel(const float* __restrict__ h0) {
    int i = blockIdx.x * 256 + threadIdx.x;
    if (i < Bb * Hh) {
        float v = h0[i];
        g_H[i] = v;
        __nv_bfloat16 hi = __float2bfloat16(v);
        g_hhi[i] = hi;
        g_hlo[i] = __float2bfloat16(v - __bfloat162float(hi));
    }
}
__global__ void copy_hT_kernel(float* __restrict__ dst) {
    int i = blockIdx.x * 256 + threadIdx.x;
    if (i < Bb * Hh) dst[i] = g_H[(size_t)Tt * Bb * Hh + i];
}

// ---------------- mma primitive ----------------
__device__ __forceinline__ void mma16816(float* c, unsigned int a0, unsigned int a1,
                                         unsigned int a2, unsigned int a3,
                                         unsigned int b0, unsigned int b1)
{
    asm volatile(
        "mma.sync.aligned.m16n8k16.row.col.f32.bf16.bf16.f32 "
        "{%0,%1,%2,%3}, {%4,%5,%6,%7}, {%8,%9}, {%0,%1,%2,%3};\n"
        : "+f"(c[0]), "+f"(c[1]), "+f"(c[2]), "+f"(c[3])
        : "r"(a0), "r"(a1), "r"(a2), "r"(a3), "r"(b0), "r"(b1));
}

// ---------------- big bf16 TC GEMM (gx_emb + logits) ----------------
__global__ __launch_bounds__(256) void bf16_mma_kernel(
    const __nv_bfloat16* __restrict__ A, const __nv_bfloat16* __restrict__ Bm,
    const float* __restrict__ bias, float* __restrict__ out, int N, int remap)
{
    __shared__ __nv_bfloat16 sA[128][40];
    __shared__ __nv_bfloat16 sB[64][40];

    const int tid = threadIdx.x;
    const int warp = tid >> 5;
    const int lane = tid & 31;
    const int wm = (warp & 3) * 32;
    const int wn = (warp >> 2) * 32;
    const int bm = blockIdx.y * 128;
    const int bn = blockIdx.x * 64;

    const int lr = tid >> 2;
    const int lc = (tid & 3) * 8;

    const __nv_bfloat16* Abase = A + (size_t)(bm + lr) * Hh + lc;
    const __nv_bfloat16* A2base = A + (size_t)(bm + lr + 64) * Hh + lc;
    const __nv_bfloat16* Bbase = Bm + (size_t)(bn + lr) * Hh + lc;

    float acc[2][4][4] = {};
    const int row = lane >> 2;
    const int kc = (lane & 3) * 2;

    for (int k0 = 0; k0 < Hh; k0 += 32) {
        *(uint4*)&sA[lr][lc]      = *(const uint4*)(Abase + k0);
        *(uint4*)&sA[lr + 64][lc] = *(const uint4*)(A2base + k0);
        *(uint4*)&sB[lr][lc]      = *(const uint4*)(Bbase + k0);
        __syncthreads();
#pragma unroll
        for (int kk = 0; kk < 32; kk += 16) {
            unsigned int a[2][4], b[4][2];
#pragma unroll
            for (int mf = 0; mf < 2; mf++) {
                int r0 = wm + mf * 16 + row;
                a[mf][0] = *(const unsigned int*)&sA[r0][kk + kc];
                a[mf][1] = *(const unsigned int*)&sA[r0 + 8][kk + kc];
                a[mf][2] = *(const unsigned int*)&sA[r0][kk + kc + 8];
                a[mf][3] = *(const unsigned int*)&sA[r0 + 8][kk + kc + 8];
            }
#pragma unroll
            for (int nf = 0; nf < 4; nf++) {
                int r0 = wn + nf * 8 + row;
                b[nf][0] = *(const unsigned int*)&sB[r0][kk + kc];
                b[nf][1] = *(const unsigned int*)&sB[r0][kk + kc + 8];
            }
#pragma unroll
            for (int mf = 0; mf < 2; mf++)
#pragma unroll
                for (int nf = 0; nf < 4; nf++)
                    mma16816(acc[mf][nf], a[mf][0], a[mf][1], a[mf][2], a[mf][3],
                             b[nf][0], b[nf][1]);
        }
        __syncthreads();
    }

#pragma unroll
    for (int mf = 0; mf < 2; mf++) {
#pragma unroll
        for (int nf = 0; nf < 4; nf++) {
            int gm = bm + wm + mf * 16 + row;
            int gn = bn + wn + nf * 8 + kc;
            float bi0 = bias[gn], bi1 = bias[gn + 1];
            int o0 = remap ? ((gm & 15) * Tt + (gm >> 4)) : gm;
            *(float2*)(out + (size_t)o0 * N + gn) =
                make_float2(acc[mf][nf][0] + bi0, acc[mf][nf][1] + bi1);
            int gm2 = gm + 8;
            int o1 = remap ? ((gm2 & 15) * Tt + (gm2 >> 4)) : gm2;
            *(float2*)(out + (size_t)o1 * N + gn) =
                make_float2(acc[mf][nf][2] + bi0, acc[mf][nf][3] + bi1);
        }
    }
}

// ------- per-step TC GEMM 1: [q | gh] = h @ [Wq; Whh]^T via hi/lo split -------
// grid 64, block 256 (8 warps x 8 N-rows); M=16, K=1024
__global__ __launch_bounds__(256) void hgemm_tc_kernel(const float* __restrict__ bhh)
{
    __shared__ __nv_bfloat16 sAh[16][40], sAl[16][40];
    __shared__ __nv_bfloat16 sBh[64][40], sBl[64][40];

    const int tid = threadIdx.x;
    const int warp = tid >> 5;
    const int lane = tid & 31;
    const int bn = blockIdx.x * 64;
    const int wn = warp * 8;
    const int lr = tid >> 2;            // 0..63
    const int lc = (tid & 3) * 8;
    const int lrA = (tid & 63) >> 2;    // 0..15
    const int row = lane >> 2;
    const int kc = (lane & 3) * 2;

    float c0[4] = {}, c1[4] = {}, c2[4] = {};

    for (int k0 = 0; k0 < Hh; k0 += 32) {
        if (tid < 64)
            *(uint4*)&sAh[lrA][lc] = *(const uint4*)(g_hhi + (size_t)lrA * Hh + k0 + lc);
        else if (tid < 128)
            *(uint4*)&sAl[lrA][lc] = *(const uint4*)(g_hlo + (size_t)lrA * Hh + k0 + lc);
        *(uint4*)&sBh[lr][lc] = *(const uint4*)(g_Wcat_hi + (size_t)(bn + lr) * Hh + k0 + lc);
        *(uint4*)&sBl[lr][lc] = *(const uint4*)(g_Wcat_lo + (size_t)(bn + lr) * Hh + k0 + lc);
        __syncthreads();
#pragma unroll
        for (int kk = 0; kk < 32; kk += 16) {
            unsigned int ah0 = *(const unsigned int*)&sAh[row][kk + kc];
            unsigned int ah1 = *(const unsigned int*)&sAh[row + 8][kk + kc];
            unsigned int ah2 = *(const unsigned int*)&sAh[row][kk + kc + 8];
            unsigned int ah3 = *(const unsigned int*)&sAh[row + 8][kk + kc + 8];
            unsigned int al0 = *(const unsigned int*)&sAl[row][kk + kc];
            unsigned int al1 = *(const unsigned int*)&sAl[row + 8][kk + kc];
            unsigned int al2 = *(const unsigned int*)&sAl[row][kk + kc + 8];
            unsigned int al3 = *(const unsigned int*)&sAl[row + 8][kk + kc + 8];
            unsigned int bh0 = *(const unsigned int*)&sBh[wn + row][kk + kc];
            unsigned int bh1 = *(const unsigned int*)&sBh[wn + row][kk + kc + 8];
            unsigned int bl0 = *(const unsigned int*)&sBl[wn + row][kk + kc];
            unsigned int bl1 = *(const unsigned int*)&sBl[wn + row][kk + kc + 8];
            mma16816(c0, ah0, ah1, ah2, ah3, bh0, bh1);
            mma16816(c1, ah0, ah1, ah2, ah3, bl0, bl1);
            mma16816(c2, al0, al1, al2, al3, bh0, bh1);
        }
        __syncthreads();
    }

    float v0 = c0[0] + c1[0] + c2[0];
    float v1 = c0[1] + c1[1] + c2[1];
    float v2 = c0[2] + c1[2] + c2[2];
    float v3 = c0[3] + c1[3] + c2[3];

    int gn = bn + wn + kc;
    if (gn < Hh) {
        *(float2*)(g_q + (size_t)row * Hh + gn)       = make_float2(v0, v1);
        *(float2*)(g_q + (size_t)(row + 8) * Hh + gn) = make_float2(v2, v3);
    } else {
        int n = gn - Hh;
        float b0 = bhh[n], b1 = bhh[n + 1];
        *(float2*)(g_gh + (size_t)row * 3 * Hh + n)       = make_float2(v0 + b0, v1 + b1);
        *(float2*)(g_gh + (size_t)(row + 8) * 3 * Hh + n) = make_float2(v2 + b0, v3 + b1);
    }
}

// ---------------- per-step: scores[b,s] = v . tanh(q[b]+kproj[b,s]) ----------
__global__ __launch_bounds__(128) void scores_kernel(const float* __restrict__ v_att)
{
    int bs = blockIdx.x;
    int b = bs >> 7;
    int h0i = threadIdx.x * 8;
    const float4* qr = (const float4*)(g_q + (size_t)b * Hh + h0i);
    const float4* kp = (const float4*)(g_kproj + (size_t)bs * Hh + h0i);
    const float4* vp = (const float4*)(v_att + h0i);
    float acc = 0.f;
#pragma unroll
    for (int u = 0; u < 2; u++) {
        float4 q4 = qr[u], k4 = kp[u], v4 = vp[u];
        acc = fmaf(v4.x, fast_tanh(q4.x + k4.x), acc);
        acc = fmaf(v4.y, fast_tanh(q4.y + k4.y), acc);
        acc = fmaf(v4.z, fast_tanh(q4.z + k4.z), acc);
        acc = fmaf(v4.w, fast_tanh(q4.w + k4.w), acc);
    }
#pragma unroll
    for (int o = 16; o; o >>= 1) acc += __shfl_xor_sync(~0u, acc, o);
    __shared__ float sr[4];
    if ((threadIdx.x & 31) == 0) sr[threadIdx.x >> 5] = acc;
    __syncthreads();
    if (threadIdx.x == 0) g_scores[bs] = sr[0] + sr[1] + sr[2] + sr[3];
}

// ------- per-step: softmax + ctx (writes ctx hi/lo bf16); store attw ---------
__global__ __launch_bounds__(128) void ctx_kernel(const float* __restrict__ enc,
                                                  float* __restrict__ attw, int t)
{
    int b = blockIdx.x, hc = blockIdx.y, tid = threadIdx.x;
    __shared__ float w[Ss];
    __shared__ float sred[4];

    float sc = g_scores[b * Ss + tid];
    float mx = sc;
#pragma unroll
    for (int o = 16; o; o >>= 1) mx = fmaxf(mx, __shfl_xor_sync(~0u, mx, o));
    if ((tid & 31) == 0) sred[tid >> 5] = mx;
    __syncthreads();
    mx = fmaxf(fmaxf(sred[0], sred[1]), fmaxf(sred[2], sred[3]));
    float e = __expf(sc - mx);
    float sm = e;
#pragma unroll
    for (int o = 16; o; o >>= 1) sm += __shfl_xor_sync(~0u, sm, o);
    __syncthreads();
    if ((tid & 31) == 0) sred[tid >> 5] = sm;
    __syncthreads();
    sm = sred[0] + sred[1] + sred[2] + sred[3];
    float wv = __fdividef(e, sm);
    w[tid] = wv;
    if (hc == 0) attw[((size_t)b * Tt + t) * Ss + tid] = wv;
    __syncthreads();

    int h = hc * 128 + tid;
    const float* ep = enc + ((size_t)b * Ss) * Hh + h;
    float acc = 0.f;
#pragma unroll 8
    for (int s = 0; s < Ss; s++) acc = fmaf(w[s], ep[(size_t)s * Hh], acc);
    __nv_bfloat16 hi = __float2bfloat16(acc);
    g_chi[b * Hh + h] = hi;
    g_clo[b * Hh + h] = __float2bfloat16(acc - __bfloat162float(hi));
}

// ------- per-step TC GEMM 2: gx_ctx = ctx @ Wc^T (permuted rows) + gate fuse --
// grid 64, block 192 (6 warps x 8 permuted rows = 48/block); M=16, K=1024
__global__ __launch_bounds__(192) void gru2_tc_kernel(int t)
{
    __shared__ __nv_bfloat16 sAh[16][40], sAl[16][40];
    __shared__ __nv_bfloat16 sBh[48][40], sBl[48][40];
    __shared__ float sgx[2][3][8][16];   // [jgl][gate][jl][m]

    const int tid = threadIdx.x;
    const int warp = tid >> 5;           // 0..5
    const int lane = tid & 31;
    const int bn = blockIdx.x * 48;      // permuted row base
    const int wn = warp * 8;
    const int lr = tid >> 2;             // 0..47
    const int lc = (tid & 3) * 8;
    const int lrA = (tid & 63) >> 2;
    const int row = lane >> 2;
    const int kc = (lane & 3) * 2;

    float c0[4] = {}, c1[4] = {}, c2[4] = {};

    for (int k0 = 0; k0 < Hh; k0 += 32) {
        if (tid < 64)
            *(uint4*)&sAh[lrA][lc] = *(const uint4*)(g_chi + (size_t)lrA * Hh + k0 + lc);
        else if (tid < 128)
            *(uint4*)&sAl[lrA][lc] = *(const uint4*)(g_clo + (size_t)lrA * Hh + k0 + lc);
        *(uint4*)&sBh[lr][lc] = *(const uint4*)(g_Wc_hi + (size_t)(bn + lr) * Hh + k0 + lc);
        *(uint4*)&sBl[lr][lc] = *(const uint4*)(g_Wc_lo + (size_t)(bn + lr) * Hh + k0 + lc);
        __syncthreads();
#pragma unroll
        for (int kk = 0; kk < 32; kk += 16) {
            unsigned int ah0 = *(const unsigned int*)&sAh[row][kk + kc];
            unsigned int ah1 = *(const unsigned int*)&sAh[row + 8][kk + kc];
            unsigned int ah2 = *(const unsigned int*)&sAh[row][kk + kc + 8];
            unsigned int ah3 = *(const unsigned int*)&sAh[row + 8][kk + kc + 8];
            unsigned int al0 = *(const unsigned int*)&sAl[row][kk + kc];
            unsigned int al1 = *(const unsigned int*)&sAl[row + 8][kk + kc];
            unsigned int al2 = *(const unsigned int*)&sAl[row][kk + kc + 8];
            unsigned int al3 = *(const unsigned int*)&sAl[row + 8][kk + kc + 8];
            unsigned int bh0 = *(const unsigned int*)&sBh[wn + row][kk + kc];
            unsigned int bh1 = *(const unsigned int*)&sBh[wn + row][kk + kc + 8];
            unsigned int bl0 = *(const unsigned int*)&sBl[wn + row][kk + kc];
            unsigned int bl1 = *(const unsigned int*)&sBl[wn + row][kk + kc + 8];
            mma16816(c0, ah0, ah1, ah2, ah3, bh0, bh1);
            mma16816(c1, ah0, ah1, ah2, ah3, bl0, bl1);
            mma16816(c2, al0, al1, al2, al3, bh0, bh1);
        }
        __syncthreads();
    }

    // warp -> (jgl = warp/3, gate = warp%3); C cols = jl, rows = m
    {
        int g = warp % 3, jgl = warp / 3;
        sgx[jgl][g][kc][row]         = c0[0] + c1[0] + c2[0];
        sgx[jgl][g][kc + 1][row]     = c0[1] + c1[1] + c2[1];
        sgx[jgl][g][kc][row + 8]     = c0[2] + c1[2] + c2[2];
        sgx[jgl][g][kc + 1][row + 8] = c0[3] + c1[3] + c2[3];
    }
    __syncthreads();

    // fused GRU gate update: block covers j in [blk*16, blk*16+16), all m
    const float* hprev = g_H + (size_t)t * Bb * Hh;
    float* hnew = g_H + (size_t)(t + 1) * Bb * Hh;
    for (int idx = tid; idx < 256; idx += 192) {
        int m = idx & 15;
        int jloc = idx >> 4;             // 0..15
        int jgl = jloc >> 3, jl = jloc & 7;
        int j = blockIdx.x * 16 + jloc;
        int r = t * Bb + m;
        const float* gxe = g_gxemb + (size_t)r * 3 * Hh;
        const float* ghp = g_gh + (size_t)m * 3 * Hh;
        float gx_r = sgx[jgl][0][jl][m] + gxe[j];
        float gx_z = sgx[jgl][1][jl][m] + gxe[Hh + j];
        float gx_n = sgx[jgl][2][jl][m] + gxe[2 * Hh + j];
        float gh_r = ghp[j];
        float gh_z = ghp[Hh + j];
        float gh_n = ghp[2 * Hh + j];
        float rg = fast_sigmoid(gx_r + gh_r);
        float z  = fast_sigmoid(gx_z + gh_z);
        float nn = fast_tanh(gx_n + rg * gh_n);
        float hp = hprev[m * Hh + j];
        float hv = (1.f - z) * nn + z * hp;
        hnew[m * Hh + j] = hv;
        g_Hbf[(size_t)r * Hh + j] = __float2bfloat16(hv);
        __nv_bfloat16 hi = __float2bfloat16(hv);
        g_hhi[m * Hh + j] = hi;
        g_hlo[m * Hh + j] = __float2bfloat16(hv - __bfloat162float(hi));
    }
}

// ---------------- final: in-place log_softmax over V per (b,t) row -----------
__global__ __launch_bounds__(256) void logsoftmax_kernel(float* __restrict__ out)
{
    float* row = out + (size_t)blockIdx.x * Vv;
    int tid = threadIdx.x;
    __shared__ float sred[8];

    float mx = -FLT_MAX;
    for (int v = tid; v < Vv; v += 256) mx = fmaxf(mx, row[v]);
#pragma unroll
    for (int o = 16; o; o >>= 1) mx = fmaxf(mx, __shfl_xor_sync(~0u, mx, o));
    if ((tid & 31) == 0) sred[tid >> 5] = mx;
    __syncthreads();
    mx = sred[0];
#pragma unroll
    for (int i = 1; i < 8; i++) mx = fmaxf(mx, sred[i]);

    float s = 0.f;
    for (int v = tid; v < Vv; v += 256) s += __expf(row[v] - mx);
#pragma unroll
    for (int o = 16; o; o >>= 1) s += __shfl_xor_sync(~0u, s, o);
    __syncthreads();
    if ((tid & 31) == 0) sred[tid >> 5] = s;
    __syncthreads();
    s = sred[0] + sred[1] + sred[2] + sred[3] + sred[4] + sred[5] + sred[6] + sred[7];

    float lse = mx + logf(s);
    for (int v = tid; v < Vv; v += 256) row[v] -= lse;
}

// ---------------- orchestration ----------------
extern "C" void kernel_launch(void* const* d_in, const int* in_sizes, int n_in,
                              void* d_out, int out_size)
{
    const float* enc  = (const float*)d_in[0];
    const float* h0   = (const float*)d_in[1];
    const int*   tgt  = (const int*)  d_in[2];
    const float* emb  = (const float*)d_in[3];
    const float* Wq   = (const float*)d_in[4];
    const float* Wk   = (const float*)d_in[5];
    const float* vat  = (const float*)d_in[6];
    const float* Wih  = (const float*)d_in[7];
    const float* Whh  = (const float*)d_in[8];
    const float* bih  = (const float*)d_in[9];
    const float* bhh  = (const float*)d_in[10];
    const float* Wout = (const float*)d_in[11];
    const float* bout = (const float*)d_in[12];

    float* out       = (float*)d_out;
    float* out_hT    = out + (size_t)Bb * Tt * Vv;
    float* out_attw  = out_hT + (size_t)Bb * Hh;

    (void)in_sizes; (void)n_in; (void)out_size;

    // Phase 0: one-time conversions / precomputes
    conv_wout_kernel<<<4096, 256>>>(Wout);
    conv_wihemb_kernel<<<3 * Hh, 256>>>(Wih);
    conv_wcat_kernel<<<4 * Hh, 256>>>(Wq, Whh);
    conv_wc_kernel<<<3 * Hh, 256>>>(Wih);
    gather_emb_kernel<<<Tt * Bb, 256>>>(emb, tgt);
    {   // gx_emb = embbf @ Wihembbf^T + bih
        __nv_bfloat16 *Abf, *Bbf;
        float* gxemb_ptr;
        cudaGetSymbolAddress((void**)&Abf, g_embbf);
        cudaGetSymbolAddress((void**)&Bbf, g_Wihembbf);
        cudaGetSymbolAddress((void**)&gxemb_ptr, g_gxemb);
        bf16_mma_kernel<<<dim3(3 * Hh / 64, (Tt * Bb) / 128), 256>>>(
            Abf, Bbf, bih, gxemb_ptr, 3 * Hh, 0);
    }
    gemm_tn_kernel<<<dim3(Hh / 64, (Bb * Ss) / 64), 256>>>(enc, Wk, Hh);
    init_h_kernel<<<(Bb * Hh + 255) / 256, 256>>>(h0);

    // Phase 2: sequential decode (all GEMMs on tensor cores via hi/lo split)
    for (int t = 0; t < Tt; t++) {
        hgemm_tc_kernel<<<64, 256>>>(bhh);
        scores_kernel<<<Bb * Ss, 128>>>(vat);
        ctx_kernel<<<dim3(Bb, 8), 128>>>(enc, out_attw, t);
        gru2_tc_kernel<<<64, 192>>>(t);
    }

    copy_hT_kernel<<<(Bb * Hh + 255) / 256, 256>>>(out_hT);

    // Phase 3: logits on tensor cores + log_softmax
    {
        __nv_bfloat16 *Abf, *Bbf;
        cudaGetSymbolAddress((void**)&Abf, g_Hbf);
        cudaGetSymbolAddress((void**)&Bbf, g_Woutbf);
        bf16_mma_kernel<<<dim3(Vv / 64, (Tt * Bb) / 128), 256>>>(
            Abf, Bbf, bout, out, Vv, 1);
    }
    logsoftmax_kernel<<<Bb * Tt, 256>>>(out);
}

// round 5
// speedup vs baseline: 1.5711x; 1.5711x over previous
#include <cuda_runtime.h>
#include <cuda_bf16.h>
#include <math.h>
#include <float.h>

#define Bb 16
#define Ss 128
#define Tt 128
#define Hh 1024
#define Vv 32000
#define BOSTOK 1

// ---------------- scratch (device globals; no allocs allowed) ----------------
__device__ float g_kproj[Bb * Ss * Hh];
__device__ float g_H[(Tt + 1) * Bb * Hh];
__device__ __nv_bfloat16 g_Hbf[Tt * Bb * Hh];
__device__ __nv_bfloat16 g_Woutbf[(size_t)Vv * Hh];
__device__ __nv_bfloat16 g_embbf[Tt * Bb * Hh];
__device__ __nv_bfloat16 g_Wihembbf[3 * Hh * Hh];
__device__ float g_gxemb[Tt * Bb * 3 * Hh];
__device__ __nv_bfloat16 g_Wcat_hi[4 * Hh * Hh];
__device__ __nv_bfloat16 g_Wcat_lo[4 * Hh * Hh];
__device__ __nv_bfloat16 g_Wc_hi[3 * Hh * Hh];
__device__ __nv_bfloat16 g_Wc_lo[3 * Hh * Hh];
__device__ __nv_bfloat16 g_hhi[Bb * Hh], g_hlo[Bb * Hh];
__device__ __nv_bfloat16 g_chi[Bb * Hh], g_clo[Bb * Hh];
__device__ float g_q2[2][Bb * Hh];          // K-split partials of q
__device__ float g_gh2[2][Bb * 3 * Hh];     // K-split partials of gh (no bias)
__device__ float g_scores[Bb * Ss];

// ---------------- math helpers ----------------
__device__ __forceinline__ float fast_tanh(float x) {
    float xc = fminf(fmaxf(x, -15.f), 15.f);
    float t = __expf(2.f * xc);
    return __fdividef(t - 1.f, t + 1.f);
}
__device__ __forceinline__ float fast_sigmoid(float x) {
    return __fdividef(1.f, 1.f + __expf(-x));
}
__device__ __forceinline__ uint2 f4_to_bf8(float4 v) {
    __nv_bfloat162 lo = __floats2bfloat162_rn(v.x, v.y);
    __nv_bfloat162 hi = __floats2bfloat162_rn(v.z, v.w);
    uint2 o;
    o.x = *(const unsigned int*)&lo;
    o.y = *(const unsigned int*)&hi;
    return o;
}

// ---------------- cp.async helpers ----------------
__device__ __forceinline__ unsigned int smem_u32p(const void* p) {
    return (unsigned int)__cvta_generic_to_shared(p);
}
#define CPA16(dst_u32, src_ptr) \
    asm volatile("cp.async.ca.shared.global [%0], [%1], 16;" :: "r"(dst_u32), "l"(src_ptr))
#define CPA_COMMIT() asm volatile("cp.async.commit_group;")
#define CPA_WAIT(n)  asm volatile("cp.async.wait_group %0;" :: "n"(n))

// ---------------- fp32 GEMM for kproj ----------------
__global__ __launch_bounds__(256) void gemm_tn_kernel(
    const float* __restrict__ A, const float* __restrict__ Bw, int K)
{
    __shared__ float sA[16][64];
    __shared__ float sB[16][64];
    const int tid = threadIdx.x;
    const int bm = blockIdx.y * 64;
    const int bn = blockIdx.x * 64;
    const int lrow = tid >> 2;
    const int lk = (tid & 3) << 2;
    const int tx = tid & 15;
    const int ty = tid >> 4;

    const float* Ap = A + (size_t)(bm + lrow) * K + lk;
    const float* Bp = Bw + (size_t)(bn + lrow) * K + lk;

    float acc[4][4] = {};
    for (int k0 = 0; k0 < K; k0 += 16) {
        float4 av = *(const float4*)(Ap + k0);
        float4 bv = *(const float4*)(Bp + k0);
        sA[lk + 0][lrow] = av.x; sA[lk + 1][lrow] = av.y;
        sA[lk + 2][lrow] = av.z; sA[lk + 3][lrow] = av.w;
        sB[lk + 0][lrow] = bv.x; sB[lk + 1][lrow] = bv.y;
        sB[lk + 2][lrow] = bv.z; sB[lk + 3][lrow] = bv.w;
        __syncthreads();
#pragma unroll
        for (int kk = 0; kk < 16; kk++) {
            float4 a = *(const float4*)&sA[kk][ty << 2];
            float4 b = *(const float4*)&sB[kk][tx << 2];
            acc[0][0] = fmaf(a.x, b.x, acc[0][0]); acc[0][1] = fmaf(a.x, b.y, acc[0][1]);
            acc[0][2] = fmaf(a.x, b.z, acc[0][2]); acc[0][3] = fmaf(a.x, b.w, acc[0][3]);
            acc[1][0] = fmaf(a.y, b.x, acc[1][0]); acc[1][1] = fmaf(a.y, b.y, acc[1][1]);
            acc[1][2] = fmaf(a.y, b.z, acc[1][2]); acc[1][3] = fmaf(a.y, b.w, acc[1][3]);
            acc[2][0] = fmaf(a.z, b.x, acc[2][0]); acc[2][1] = fmaf(a.z, b.y, acc[2][1]);
            acc[2][2] = fmaf(a.z, b.z, acc[2][2]); acc[2][3] = fmaf(a.z, b.w, acc[2][3]);
            acc[3][0] = fmaf(a.w, b.x, acc[3][0]); acc[3][1] = fmaf(a.w, b.y, acc[3][1]);
            acc[3][2] = fmaf(a.w, b.z, acc[3][2]); acc[3][3] = fmaf(a.w, b.w, acc[3][3]);
        }
        __syncthreads();
    }
#pragma unroll
    for (int i = 0; i < 4; i++) {
        int m = bm + (ty << 2) + i;
        int n = bn + (tx << 2);
        *(float4*)(g_kproj + (size_t)m * Hh + n) =
            make_float4(acc[i][0], acc[i][1], acc[i][2], acc[i][3]);
    }
}

// ---------------- one-time conversions / gathers ----------------
__global__ __launch_bounds__(256) void conv_wout_kernel(const float* __restrict__ W)
{
    size_t n4 = (size_t)Vv * Hh / 4;
    uint2* dst = (uint2*)g_Woutbf;
    const float4* src = (const float4*)W;
    for (size_t i = blockIdx.x * 256 + threadIdx.x; i < n4; i += (size_t)gridDim.x * 256)
        dst[i] = f4_to_bf8(src[i]);
}

__global__ __launch_bounds__(256) void conv_wihemb_kernel(const float* __restrict__ Wih)
{
    int j = blockIdx.x;
    int c = threadIdx.x * 4;
    float4 v = *(const float4*)(Wih + (size_t)j * (2 * Hh) + c);
    *(uint2*)(g_Wihembbf + (size_t)j * Hh + c) = f4_to_bf8(v);
}

__device__ __forceinline__ void split_f4(float4 v, uint2* hi, uint2* lo)
{
    __nv_bfloat16 hx = __float2bfloat16(v.x), hy = __float2bfloat16(v.y);
    __nv_bfloat16 hz = __float2bfloat16(v.z), hw = __float2bfloat16(v.w);
    float4 r = make_float4(v.x - __bfloat162float(hx), v.y - __bfloat162float(hy),
                           v.z - __bfloat162float(hz), v.w - __bfloat162float(hw));
    __nv_bfloat162 h01; h01.x = hx; h01.y = hy;
    __nv_bfloat162 h23; h23.x = hz; h23.y = hw;
    uint2 h; h.x = *(unsigned int*)&h01; h.y = *(unsigned int*)&h23;
    *hi = h;
    *lo = f4_to_bf8(r);
}

__global__ __launch_bounds__(256) void conv_wcat_kernel(
    const float* __restrict__ Wq, const float* __restrict__ Whh)
{
    int r = blockIdx.x;
    const float* src = (r < Hh) ? (Wq + (size_t)r * Hh) : (Whh + (size_t)(r - Hh) * Hh);
    int c = threadIdx.x * 4;
    float4 v = *(const float4*)(src + c);
    uint2 hi, lo;
    split_f4(v, &hi, &lo);
    *(uint2*)(g_Wcat_hi + (size_t)r * Hh + c) = hi;
    *(uint2*)(g_Wcat_lo + (size_t)r * Hh + c) = lo;
}

// ctx half of Wih -> hi/lo, gate-permuted rows: rp = ((j>>3)*3+g)*8 + (j&7)
__global__ __launch_bounds__(256) void conv_wc_kernel(const float* __restrict__ Wih)
{
    int rp = blockIdx.x;
    int jl = rp & 7;
    int q = rp >> 3;
    int g = q % 3;
    int jg = q / 3;
    int j = jg * 8 + jl;
    const float* src = Wih + (size_t)(g * Hh + j) * (2 * Hh) + Hh;
    int c = threadIdx.x * 4;
    float4 v = *(const float4*)(src + c);
    uint2 hi, lo;
    split_f4(v, &hi, &lo);
    *(uint2*)(g_Wc_hi + (size_t)rp * Hh + c) = hi;
    *(uint2*)(g_Wc_lo + (size_t)rp * Hh + c) = lo;
}

__global__ __launch_bounds__(256) void gather_emb_kernel(
    const float* __restrict__ emb, const int* __restrict__ tgt)
{
    int r = blockIdx.x;
    int t = r >> 4, b = r & 15;
    int tok = (t == 0) ? BOSTOK : tgt[b * Tt + (t - 1)];
    int c = threadIdx.x * 4;
    float4 v = *(const float4*)(emb + (size_t)tok * Hh + c);
    *(uint2*)(g_embbf + (size_t)r * Hh + c) = f4_to_bf8(v);
}

// ---------------- h0 init / hT copy ----------------
__global__ void init_h_kernel(const float* __restrict__ h0) {
    int i = blockIdx.x * 256 + threadIdx.x;
    if (i < Bb * Hh) {
        float v = h0[i];
        g_H[i] = v;
        __nv_bfloat16 hi = __float2bfloat16(v);
        g_hhi[i] = hi;
        g_hlo[i] = __float2bfloat16(v - __bfloat162float(hi));
    }
}
__global__ void copy_hT_kernel(float* __restrict__ dst) {
    int i = blockIdx.x * 256 + threadIdx.x;
    if (i < Bb * Hh) dst[i] = g_H[(size_t)Tt * Bb * Hh + i];
}

// ---------------- mma primitive ----------------
__device__ __forceinline__ void mma16816(float* c, unsigned int a0, unsigned int a1,
                                         unsigned int a2, unsigned int a3,
                                         unsigned int b0, unsigned int b1)
{
    asm volatile(
        "mma.sync.aligned.m16n8k16.row.col.f32.bf16.bf16.f32 "
        "{%0,%1,%2,%3}, {%4,%5,%6,%7}, {%8,%9}, {%0,%1,%2,%3};\n"
        : "+f"(c[0]), "+f"(c[1]), "+f"(c[2]), "+f"(c[3])
        : "r"(a0), "r"(a1), "r"(a2), "r"(a3), "r"(b0), "r"(b1));
}

// ---------------- big bf16 TC GEMM (gx_emb + logits) ----------------
__global__ __launch_bounds__(256) void bf16_mma_kernel(
    const __nv_bfloat16* __restrict__ A, const __nv_bfloat16* __restrict__ Bm,
    const float* __restrict__ bias, float* __restrict__ out, int N, int remap)
{
    __shared__ __align__(16) __nv_bfloat16 sA[128][40];
    __shared__ __align__(16) __nv_bfloat16 sB[64][40];

    const int tid = threadIdx.x;
    const int warp = tid >> 5;
    const int lane = tid & 31;
    const int wm = (warp & 3) * 32;
    const int wn = (warp >> 2) * 32;
    const int bm = blockIdx.y * 128;
    const int bn = blockIdx.x * 64;

    const int lr = tid >> 2;
    const int lc = (tid & 3) * 8;

    const __nv_bfloat16* Abase = A + (size_t)(bm + lr) * Hh + lc;
    const __nv_bfloat16* A2base = A + (size_t)(bm + lr + 64) * Hh + lc;
    const __nv_bfloat16* Bbase = Bm + (size_t)(bn + lr) * Hh + lc;

    float acc[2][4][4] = {};
    const int row = lane >> 2;
    const int kc = (lane & 3) * 2;

    for (int k0 = 0; k0 < Hh; k0 += 32) {
        *(uint4*)&sA[lr][lc]      = *(const uint4*)(Abase + k0);
        *(uint4*)&sA[lr + 64][lc] = *(const uint4*)(A2base + k0);
        *(uint4*)&sB[lr][lc]      = *(const uint4*)(Bbase + k0);
        __syncthreads();
#pragma unroll
        for (int kk = 0; kk < 32; kk += 16) {
            unsigned int a[2][4], b[4][2];
#pragma unroll
            for (int mf = 0; mf < 2; mf++) {
                int r0 = wm + mf * 16 + row;
                a[mf][0] = *(const unsigned int*)&sA[r0][kk + kc];
                a[mf][1] = *(const unsigned int*)&sA[r0 + 8][kk + kc];
                a[mf][2] = *(const unsigned int*)&sA[r0][kk + kc + 8];
                a[mf][3] = *(const unsigned int*)&sA[r0 + 8][kk + kc + 8];
            }
#pragma unroll
            for (int nf = 0; nf < 4; nf++) {
                int r0 = wn + nf * 8 + row;
                b[nf][0] = *(const unsigned int*)&sB[r0][kk + kc];
                b[nf][1] = *(const unsigned int*)&sB[r0][kk + kc + 8];
            }
#pragma unroll
            for (int mf = 0; mf < 2; mf++)
#pragma unroll
                for (int nf = 0; nf < 4; nf++)
                    mma16816(acc[mf][nf], a[mf][0], a[mf][1], a[mf][2], a[mf][3],
                             b[nf][0], b[nf][1]);
        }
        __syncthreads();
    }

#pragma unroll
    for (int mf = 0; mf < 2; mf++) {
#pragma unroll
        for (int nf = 0; nf < 4; nf++) {
            int gm = bm + wm + mf * 16 + row;
            int gn = bn + wn + nf * 8 + kc;
            float bi0 = bias[gn], bi1 = bias[gn + 1];
            int o0 = remap ? ((gm & 15) * Tt + (gm >> 4)) : gm;
            *(float2*)(out + (size_t)o0 * N + gn) =
                make_float2(acc[mf][nf][0] + bi0, acc[mf][nf][1] + bi1);
            int gm2 = gm + 8;
            int o1 = remap ? ((gm2 & 15) * Tt + (gm2 >> 4)) : gm2;
            *(float2*)(out + (size_t)o1 * N + gn) =
                make_float2(acc[mf][nf][2] + bi0, acc[mf][nf][3] + bi1);
        }
    }
}

// ------- per-step TC GEMM 1: [q | gh] partials, K-split 2, cp.async 2-stage ---
// grid 128 (64 n-tiles x 2 k-splits), block 256 (8 warps x 8 N rows)
__global__ __launch_bounds__(256) void hgemm_tc_kernel()
{
    __shared__ __align__(16) __nv_bfloat16 sAh[2][16][40], sAl[2][16][40];
    __shared__ __align__(16) __nv_bfloat16 sBh[2][64][40], sBl[2][64][40];

    const int tid = threadIdx.x;
    const int warp = tid >> 5;
    const int lane = tid & 31;
    const int nt = blockIdx.x & 63;
    const int ks = blockIdx.x >> 6;
    const int bn = nt * 64;
    const int kbase = ks * 512;
    const int wn = warp * 8;
    const int lr = tid >> 2;
    const int lc = (tid & 3) * 8;
    const int lrA = (tid & 63) >> 2;
    const int row = lane >> 2;
    const int kc = (lane & 3) * 2;

    const __nv_bfloat16* gBh = g_Wcat_hi + (size_t)(bn + lr) * Hh + kbase + lc;
    const __nv_bfloat16* gBl = g_Wcat_lo + (size_t)(bn + lr) * Hh + kbase + lc;
    const __nv_bfloat16* gA = (tid < 128)
        ? ((tid < 64 ? g_hhi : g_hlo) + (size_t)lrA * Hh + kbase + lc) : g_hhi;

    auto issue = [&](int st, int k0) {
        if (tid < 64)       CPA16(smem_u32p(&sAh[st][lrA][lc]), gA + k0);
        else if (tid < 128) CPA16(smem_u32p(&sAl[st][lrA][lc]), gA + k0);
        CPA16(smem_u32p(&sBh[st][lr][lc]), gBh + k0);
        CPA16(smem_u32p(&sBl[st][lr][lc]), gBl + k0);
        CPA_COMMIT();
    };

    float c0[4] = {}, c1[4] = {}, c2[4] = {};
    issue(0, 0);
#pragma unroll 4
    for (int k = 0; k < 16; k++) {
        const int st = k & 1;
        if (k + 1 < 16) { issue(st ^ 1, (k + 1) * 32); CPA_WAIT(1); }
        else            { CPA_WAIT(0); }
        __syncthreads();
#pragma unroll
        for (int kk = 0; kk < 32; kk += 16) {
            unsigned int ah0 = *(const unsigned int*)&sAh[st][row][kk + kc];
            unsigned int ah1 = *(const unsigned int*)&sAh[st][row + 8][kk + kc];
            unsigned int ah2 = *(const unsigned int*)&sAh[st][row][kk + kc + 8];
            unsigned int ah3 = *(const unsigned int*)&sAh[st][row + 8][kk + kc + 8];
            unsigned int al0 = *(const unsigned int*)&sAl[st][row][kk + kc];
            unsigned int al1 = *(const unsigned int*)&sAl[st][row + 8][kk + kc];
            unsigned int al2 = *(const unsigned int*)&sAl[st][row][kk + kc + 8];
            unsigned int al3 = *(const unsigned int*)&sAl[st][row + 8][kk + kc + 8];
            unsigned int bh0 = *(const unsigned int*)&sBh[st][wn + row][kk + kc];
            unsigned int bh1 = *(const unsigned int*)&sBh[st][wn + row][kk + kc + 8];
            unsigned int bl0 = *(const unsigned int*)&sBl[st][wn + row][kk + kc];
            unsigned int bl1 = *(const unsigned int*)&sBl[st][wn + row][kk + kc + 8];
            mma16816(c0, ah0, ah1, ah2, ah3, bh0, bh1);
            mma16816(c1, ah0, ah1, ah2, ah3, bl0, bl1);
            mma16816(c2, al0, al1, al2, al3, bh0, bh1);
        }
        __syncthreads();
    }

    float v0 = c0[0] + c1[0] + c2[0];
    float v1 = c0[1] + c1[1] + c2[1];
    float v2 = c0[2] + c1[2] + c2[2];
    float v3 = c0[3] + c1[3] + c2[3];

    int gn = bn + wn + kc;
    if (gn < Hh) {
        float* qd = g_q2[ks];
        *(float2*)(qd + (size_t)row * Hh + gn)       = make_float2(v0, v1);
        *(float2*)(qd + (size_t)(row + 8) * Hh + gn) = make_float2(v2, v3);
    } else {
        int n = gn - Hh;
        float* gd = g_gh2[ks];
        *(float2*)(gd + (size_t)row * 3 * Hh + n)       = make_float2(v0, v1);
        *(float2*)(gd + (size_t)(row + 8) * 3 * Hh + n) = make_float2(v2, v3);
    }
}

// ---------------- per-step: scores[b,s] = v . tanh(q0+q1+kproj) --------------
__global__ __launch_bounds__(128) void scores_kernel(const float* __restrict__ v_att)
{
    int bs = blockIdx.x;
    int b = bs >> 7;
    int h0i = threadIdx.x * 8;
    const float4* q0 = (const float4*)(g_q2[0] + (size_t)b * Hh + h0i);
    const float4* q1 = (const float4*)(g_q2[1] + (size_t)b * Hh + h0i);
    const float4* kp = (const float4*)(g_kproj + (size_t)bs * Hh + h0i);
    const float4* vp = (const float4*)(v_att + h0i);
    float acc = 0.f;
#pragma unroll
    for (int u = 0; u < 2; u++) {
        float4 qa = q0[u], qb = q1[u], k4 = kp[u], v4 = vp[u];
        acc = fmaf(v4.x, fast_tanh(qa.x + qb.x + k4.x), acc);
        acc = fmaf(v4.y, fast_tanh(qa.y + qb.y + k4.y), acc);
        acc = fmaf(v4.z, fast_tanh(qa.z + qb.z + k4.z), acc);
        acc = fmaf(v4.w, fast_tanh(qa.w + qb.w + k4.w), acc);
    }
#pragma unroll
    for (int o = 16; o; o >>= 1) acc += __shfl_xor_sync(~0u, acc, o);
    __shared__ float sr[4];
    if ((threadIdx.x & 31) == 0) sr[threadIdx.x >> 5] = acc;
    __syncthreads();
    if (threadIdx.x == 0) g_scores[bs] = sr[0] + sr[1] + sr[2] + sr[3];
}

// ------- per-step: softmax + ctx (writes ctx hi/lo bf16); store attw ---------
__global__ __launch_bounds__(128) void ctx_kernel(const float* __restrict__ enc,
                                                  float* __restrict__ attw, int t)
{
    int b = blockIdx.x, hc = blockIdx.y, tid = threadIdx.x;
    __shared__ float w[Ss];
    __shared__ float sred[4];

    float sc = g_scores[b * Ss + tid];
    float mx = sc;
#pragma unroll
    for (int o = 16; o; o >>= 1) mx = fmaxf(mx, __shfl_xor_sync(~0u, mx, o));
    if ((tid & 31) == 0) sred[tid >> 5] = mx;
    __syncthreads();
    mx = fmaxf(fmaxf(sred[0], sred[1]), fmaxf(sred[2], sred[3]));
    float e = __expf(sc - mx);
    float sm = e;
#pragma unroll
    for (int o = 16; o; o >>= 1) sm += __shfl_xor_sync(~0u, sm, o);
    __syncthreads();
    if ((tid & 31) == 0) sred[tid >> 5] = sm;
    __syncthreads();
    sm = sred[0] + sred[1] + sred[2] + sred[3];
    float wv = __fdividef(e, sm);
    w[tid] = wv;
    if (hc == 0) attw[((size_t)b * Tt + t) * Ss + tid] = wv;
    __syncthreads();

    int h = hc * 128 + tid;
    const float* ep = enc + ((size_t)b * Ss) * Hh + h;
    float acc = 0.f;
#pragma unroll 8
    for (int s = 0; s < Ss; s++) acc = fmaf(w[s], ep[(size_t)s * Hh], acc);
    __nv_bfloat16 hi = __float2bfloat16(acc);
    g_chi[b * Hh + h] = hi;
    g_clo[b * Hh + h] = __float2bfloat16(acc - __bfloat162float(hi));
}

// ------- per-step TC GEMM 2: gx_ctx + fused gate update, cp.async 2-stage ----
// grid 64, block 192 (6 warps x 8 permuted rows)
__global__ __launch_bounds__(192) void gru2_tc_kernel(const float* __restrict__ bhh, int t)
{
    __shared__ __align__(16) __nv_bfloat16 sAh[2][16][40], sAl[2][16][40];
    __shared__ __align__(16) __nv_bfloat16 sBh[2][48][40], sBl[2][48][40];
    __shared__ float sgx[2][3][8][16];   // [jgl][gate][jl][m]

    const int tid = threadIdx.x;
    const int warp = tid >> 5;
    const int lane = tid & 31;
    const int bn = blockIdx.x * 48;
    const int wn = warp * 8;
    const int lr = tid >> 2;             // 0..47
    const int lc = (tid & 3) * 8;
    const int lrA = (tid & 63) >> 2;
    const int row = lane >> 2;
    const int kc = (lane & 3) * 2;

    const __nv_bfloat16* gBh = g_Wc_hi + (size_t)(bn + lr) * Hh + lc;
    const __nv_bfloat16* gBl = g_Wc_lo + (size_t)(bn + lr) * Hh + lc;
    const __nv_bfloat16* gA = (tid < 128)
        ? ((tid < 64 ? g_chi : g_clo) + (size_t)lrA * Hh + lc) : g_chi;

    auto issue = [&](int st, int k0) {
        if (tid < 64)       CPA16(smem_u32p(&sAh[st][lrA][lc]), gA + k0);
        else if (tid < 128) CPA16(smem_u32p(&sAl[st][lrA][lc]), gA + k0);
        CPA16(smem_u32p(&sBh[st][lr][lc]), gBh + k0);
        CPA16(smem_u32p(&sBl[st][lr][lc]), gBl + k0);
        CPA_COMMIT();
    };

    float c0[4] = {}, c1[4] = {}, c2[4] = {};
    issue(0, 0);
#pragma unroll 4
    for (int k = 0; k < 32; k++) {
        const int st = k & 1;
        if (k + 1 < 32) { issue(st ^ 1, (k + 1) * 32); CPA_WAIT(1); }
        else            { CPA_WAIT(0); }
        __syncthreads();
#pragma unroll
        for (int kk = 0; kk < 32; kk += 16) {
            unsigned int ah0 = *(const unsigned int*)&sAh[st][row][kk + kc];
            unsigned int ah1 = *(const unsigned int*)&sAh[st][row + 8][kk + kc];
            unsigned int ah2 = *(const unsigned int*)&sAh[st][row][kk + kc + 8];
            unsigned int ah3 = *(const unsigned int*)&sAh[st][row + 8][kk + kc + 8];
            unsigned int al0 = *(const unsigned int*)&sAl[st][row][kk + kc];
            unsigned int al1 = *(const unsigned int*)&sAl[st][row + 8][kk + kc];
            unsigned int al2 = *(const unsigned int*)&sAl[st][row][kk + kc + 8];
            unsigned int al3 = *(const unsigned int*)&sAl[st][row + 8][kk + kc + 8];
            unsigned int bh0 = *(const unsigned int*)&sBh[st][wn + row][kk + kc];
            unsigned int bh1 = *(const unsigned int*)&sBh[st][wn + row][kk + kc + 8];
            unsigned int bl0 = *(const unsigned int*)&sBl[st][wn + row][kk + kc];
            unsigned int bl1 = *(const unsigned int*)&sBl[st][wn + row][kk + kc + 8];
            mma16816(c0, ah0, ah1, ah2, ah3, bh0, bh1);
            mma16816(c1, ah0, ah1, ah2, ah3, bl0, bl1);
            mma16816(c2, al0, al1, al2, al3, bh0, bh1);
        }
        __syncthreads();
    }

    {
        int g = warp % 3, jgl = warp / 3;
        sgx[jgl][g][kc][row]         = c0[0] + c1[0] + c2[0];
        sgx[jgl][g][kc + 1][row]     = c0[1] + c1[1] + c2[1];
        sgx[jgl][g][kc][row + 8]     = c0[2] + c1[2] + c2[2];
        sgx[jgl][g][kc + 1][row + 8] = c0[3] + c1[3] + c2[3];
    }
    __syncthreads();

    const float* hprev = g_H + (size_t)t * Bb * Hh;
    float* hnew = g_H + (size_t)(t + 1) * Bb * Hh;
    for (int idx = tid; idx < 256; idx += 192) {
        int m = idx & 15;
        int jloc = idx >> 4;
        int jgl = jloc >> 3, jl = jloc & 7;
        int j = blockIdx.x * 16 + jloc;
        int r = t * Bb + m;
        const float* gxe = g_gxemb + (size_t)r * 3 * Hh;
        const float* g0 = g_gh2[0] + (size_t)m * 3 * Hh;
        const float* g1 = g_gh2[1] + (size_t)m * 3 * Hh;
        float gx_r = sgx[jgl][0][jl][m] + gxe[j];
        float gx_z = sgx[jgl][1][jl][m] + gxe[Hh + j];
        float gx_n = sgx[jgl][2][jl][m] + gxe[2 * Hh + j];
        float gh_r = g0[j]          + g1[j]          + bhh[j];
        float gh_z = g0[Hh + j]     + g1[Hh + j]     + bhh[Hh + j];
        float gh_n = g0[2 * Hh + j] + g1[2 * Hh + j] + bhh[2 * Hh + j];
        float rg = fast_sigmoid(gx_r + gh_r);
        float z  = fast_sigmoid(gx_z + gh_z);
        float nn = fast_tanh(gx_n + rg * gh_n);
        float hp = hprev[m * Hh + j];
        float hv = (1.f - z) * nn + z * hp;
        hnew[m * Hh + j] = hv;
        g_Hbf[(size_t)r * Hh + j] = __float2bfloat16(hv);
        __nv_bfloat16 hi = __float2bfloat16(hv);
        g_hhi[m * Hh + j] = hi;
        g_hlo[m * Hh + j] = __float2bfloat16(hv - __bfloat162float(hi));
    }
}

// ---------------- final: in-place log_softmax over V per (b,t) row -----------
__global__ __launch_bounds__(256) void logsoftmax_kernel(float* __restrict__ out)
{
    float* row = out + (size_t)blockIdx.x * Vv;
    int tid = threadIdx.x;
    __shared__ float sred[8];

    float mx = -FLT_MAX;
    for (int v = tid; v < Vv; v += 256) mx = fmaxf(mx, row[v]);
#pragma unroll
    for (int o = 16; o; o >>= 1) mx = fmaxf(mx, __shfl_xor_sync(~0u, mx, o));
    if ((tid & 31) == 0) sred[tid >> 5] = mx;
    __syncthreads();
    mx = sred[0];
#pragma unroll
    for (int i = 1; i < 8; i++) mx = fmaxf(mx, sred[i]);

    float s = 0.f;
    for (int v = tid; v < Vv; v += 256) s += __expf(row[v] - mx);
#pragma unroll
    for (int o = 16; o; o >>= 1) s += __shfl_xor_sync(~0u, s, o);
    __syncthreads();
    if ((tid & 31) == 0) sred[tid >> 5] = s;
    __syncthreads();
    s = sred[0] + sred[1] + sred[2] + sred[3] + sred[4] + sred[5] + sred[6] + sred[7];

    float lse = mx + logf(s);
    for (int v = tid; v < Vv; v += 256) row[v] -= lse;
}

// ---------------- orchestration ----------------
extern "C" void kernel_launch(void* const* d_in, const int* in_sizes, int n_in,
                              void* d_out, int out_size)
{
    const float* enc  = (const float*)d_in[0];
    const float* h0   = (const float*)d_in[1];
    const int*   tgt  = (const int*)  d_in[2];
    const float* emb  = (const float*)d_in[3];
    const float* Wq   = (const float*)d_in[4];
    const float* Wk   = (const float*)d_in[5];
    const float* vat  = (const float*)d_in[6];
    const float* Wih  = (const float*)d_in[7];
    const float* Whh  = (const float*)d_in[8];
    const float* bih  = (const float*)d_in[9];
    const float* bhh  = (const float*)d_in[10];
    const float* Wout = (const float*)d_in[11];
    const float* bout = (const float*)d_in[12];

    float* out       = (float*)d_out;
    float* out_hT    = out + (size_t)Bb * Tt * Vv;
    float* out_attw  = out_hT + (size_t)Bb * Hh;

    (void)in_sizes; (void)n_in; (void)out_size;

    // Phase 0: one-time conversions / precomputes
    conv_wout_kernel<<<4096, 256>>>(Wout);
    conv_wihemb_kernel<<<3 * Hh, 256>>>(Wih);
    conv_wcat_kernel<<<4 * Hh, 256>>>(Wq, Whh);
    conv_wc_kernel<<<3 * Hh, 256>>>(Wih);
    gather_emb_kernel<<<Tt * Bb, 256>>>(emb, tgt);
    {
        __nv_bfloat16 *Abf, *Bbf;
        float* gxemb_ptr;
        cudaGetSymbolAddress((void**)&Abf, g_embbf);
        cudaGetSymbolAddress((void**)&Bbf, g_Wihembbf);
        cudaGetSymbolAddress((void**)&gxemb_ptr, g_gxemb);
        bf16_mma_kernel<<<dim3(3 * Hh / 64, (Tt * Bb) / 128), 256>>>(
            Abf, Bbf, bih, gxemb_ptr, 3 * Hh, 0);
    }
    gemm_tn_kernel<<<dim3(Hh / 64, (Bb * Ss) / 64), 256>>>(enc, Wk, Hh);
    init_h_kernel<<<(Bb * Hh + 255) / 256, 256>>>(h0);

    // Phase 2: sequential decode (pipelined TC GEMMs)
    for (int t = 0; t < Tt; t++) {
        hgemm_tc_kernel<<<128, 256>>>();
        scores_kernel<<<Bb * Ss, 128>>>(vat);
        ctx_kernel<<<dim3(Bb, 8), 128>>>(enc, out_attw, t);
        gru2_tc_kernel<<<64, 192>>>(bhh, t);
    }

    copy_hT_kernel<<<(Bb * Hh + 255) / 256, 256>>>(out_hT);

    // Phase 3: logits on tensor cores + log_softmax
    {
        __nv_bfloat16 *Abf, *Bbf;
        cudaGetSymbolAddress((void**)&Abf, g_Hbf);
        cudaGetSymbolAddress((void**)&Bbf, g_Woutbf);
        bf16_mma_kernel<<<dim3(Vv / 64, (Tt * Bb) / 128), 256>>>(
            Abf, Bbf, bout, out, Vv, 1);
    }
    logsoftmax_kernel<<<Bb * Tt, 256>>>(out);
}

// round 6
// speedup vs baseline: 1.5755x; 1.0028x over previous
#include <cuda_runtime.h>
#include <cuda_bf16.h>
#include <math.h>
#include <float.h>

#define Bb 16
#define Ss 128
#define Tt 128
#define Hh 1024
#define Vv 32000
#define BOSTOK 1
#define GRIDB 128u

// ---------------- scratch (device globals; no allocs allowed) ----------------
__device__ float g_kproj[Bb * Ss * Hh];
__device__ float g_H[(Tt + 1) * Bb * Hh];
__device__ __nv_bfloat16 g_Hbf[Tt * Bb * Hh];
__device__ __nv_bfloat16 g_Woutbf[(size_t)Vv * Hh];
__device__ __nv_bfloat16 g_embbf[Tt * Bb * Hh];
__device__ __nv_bfloat16 g_Wihembbf[3 * Hh * Hh];
__device__ float g_gxemb[Tt * Bb * 3 * Hh];
__device__ __nv_bfloat16 g_Wcat_hi[4 * Hh * Hh];
__device__ __nv_bfloat16 g_Wcat_lo[4 * Hh * Hh];
__device__ __nv_bfloat16 g_Wc_hi[3 * Hh * Hh];
__device__ __nv_bfloat16 g_Wc_lo[3 * Hh * Hh];
__device__ __nv_bfloat16 g_hhi[Bb * Hh], g_hlo[Bb * Hh];
__device__ __nv_bfloat16 g_chi[Bb * Hh], g_clo[Bb * Hh];
__device__ float g_q2[2][Bb * Hh];
__device__ float g_gh2[2][Bb * 3 * Hh];
__device__ float g_scores[Bb * Ss];
__device__ unsigned g_barcnt;

// ---------------- math helpers ----------------
__device__ __forceinline__ float fast_tanh(float x) {
    float xc = fminf(fmaxf(x, -15.f), 15.f);
    float t = __expf(2.f * xc);
    return __fdividef(t - 1.f, t + 1.f);
}
__device__ __forceinline__ float fast_sigmoid(float x) {
    return __fdividef(1.f, 1.f + __expf(-x));
}
__device__ __forceinline__ float tanh_approx(float x) {
    float y;
    asm("tanh.approx.f32 %0, %1;" : "=f"(y) : "f"(x));
    return y;
}
__device__ __forceinline__ uint2 f4_to_bf8(float4 v) {
    __nv_bfloat162 lo = __floats2bfloat162_rn(v.x, v.y);
    __nv_bfloat162 hi = __floats2bfloat162_rn(v.z, v.w);
    uint2 o;
    o.x = *(const unsigned int*)&lo;
    o.y = *(const unsigned int*)&hi;
    return o;
}

// ---------------- cp.async helpers ----------------
__device__ __forceinline__ unsigned int smem_u32p(const void* p) {
    return (unsigned int)__cvta_generic_to_shared(p);
}
#define CPA16(dst_u32, src_ptr) \
    asm volatile("cp.async.ca.shared.global [%0], [%1], 16;" :: "r"(dst_u32), "l"(src_ptr))
#define CPA16CG(dst_u32, src_ptr) \
    asm volatile("cp.async.cg.shared.global [%0], [%1], 16;" :: "r"(dst_u32), "l"(src_ptr))
#define CPA_COMMIT() asm volatile("cp.async.commit_group;")
#define CPA_WAIT(n)  asm volatile("cp.async.wait_group %0;" :: "n"(n))

// ---------------- software grid barrier (all GRIDB blocks resident) ----------
__device__ __forceinline__ void gbar(unsigned& bo) {
    bo += GRIDB;
    __syncthreads();
    if (threadIdx.x == 0) {
        __threadfence();
        atomicAdd(&g_barcnt, 1u);
        while (*((volatile unsigned*)&g_barcnt) < bo) { }
        __threadfence();
    }
    __syncthreads();
}

// ---------------- fp32 GEMM for kproj ----------------
__global__ __launch_bounds__(256) void gemm_tn_kernel(
    const float* __restrict__ A, const float* __restrict__ Bw, int K)
{
    __shared__ float sA[16][64];
    __shared__ float sB[16][64];
    const int tid = threadIdx.x;
    const int bm = blockIdx.y * 64;
    const int bn = blockIdx.x * 64;
    const int lrow = tid >> 2;
    const int lk = (tid & 3) << 2;
    const int tx = tid & 15;
    const int ty = tid >> 4;

    const float* Ap = A + (size_t)(bm + lrow) * K + lk;
    const float* Bp = Bw + (size_t)(bn + lrow) * K + lk;

    float acc[4][4] = {};
    for (int k0 = 0; k0 < K; k0 += 16) {
        float4 av = *(const float4*)(Ap + k0);
        float4 bv = *(const float4*)(Bp + k0);
        sA[lk + 0][lrow] = av.x; sA[lk + 1][lrow] = av.y;
        sA[lk + 2][lrow] = av.z; sA[lk + 3][lrow] = av.w;
        sB[lk + 0][lrow] = bv.x; sB[lk + 1][lrow] = bv.y;
        sB[lk + 2][lrow] = bv.z; sB[lk + 3][lrow] = bv.w;
        __syncthreads();
#pragma unroll
        for (int kk = 0; kk < 16; kk++) {
            float4 a = *(const float4*)&sA[kk][ty << 2];
            float4 b = *(const float4*)&sB[kk][tx << 2];
            acc[0][0] = fmaf(a.x, b.x, acc[0][0]); acc[0][1] = fmaf(a.x, b.y, acc[0][1]);
            acc[0][2] = fmaf(a.x, b.z, acc[0][2]); acc[0][3] = fmaf(a.x, b.w, acc[0][3]);
            acc[1][0] = fmaf(a.y, b.x, acc[1][0]); acc[1][1] = fmaf(a.y, b.y, acc[1][1]);
            acc[1][2] = fmaf(a.y, b.z, acc[1][2]); acc[1][3] = fmaf(a.y, b.w, acc[1][3]);
            acc[2][0] = fmaf(a.z, b.x, acc[2][0]); acc[2][1] = fmaf(a.z, b.y, acc[2][1]);
            acc[2][2] = fmaf(a.z, b.z, acc[2][2]); acc[2][3] = fmaf(a.z, b.w, acc[2][3]);
            acc[3][0] = fmaf(a.w, b.x, acc[3][0]); acc[3][1] = fmaf(a.w, b.y, acc[3][1]);
            acc[3][2] = fmaf(a.w, b.z, acc[3][2]); acc[3][3] = fmaf(a.w, b.w, acc[3][3]);
        }
        __syncthreads();
    }
#pragma unroll
    for (int i = 0; i < 4; i++) {
        int m = bm + (ty << 2) + i;
        int n = bn + (tx << 2);
        *(float4*)(g_kproj + (size_t)m * Hh + n) =
            make_float4(acc[i][0], acc[i][1], acc[i][2], acc[i][3]);
    }
}

// ---------------- one-time conversions / gathers ----------------
__global__ __launch_bounds__(256) void conv_wout_kernel(const float* __restrict__ W)
{
    size_t n4 = (size_t)Vv * Hh / 4;
    uint2* dst = (uint2*)g_Woutbf;
    const float4* src = (const float4*)W;
    for (size_t i = blockIdx.x * 256 + threadIdx.x; i < n4; i += (size_t)gridDim.x * 256)
        dst[i] = f4_to_bf8(src[i]);
}

__global__ __launch_bounds__(256) void conv_wihemb_kernel(const float* __restrict__ Wih)
{
    int j = blockIdx.x;
    int c = threadIdx.x * 4;
    float4 v = *(const float4*)(Wih + (size_t)j * (2 * Hh) + c);
    *(uint2*)(g_Wihembbf + (size_t)j * Hh + c) = f4_to_bf8(v);
}

__device__ __forceinline__ void split_f4(float4 v, uint2* hi, uint2* lo)
{
    __nv_bfloat16 hx = __float2bfloat16(v.x), hy = __float2bfloat16(v.y);
    __nv_bfloat16 hz = __float2bfloat16(v.z), hw = __float2bfloat16(v.w);
    float4 r = make_float4(v.x - __bfloat162float(hx), v.y - __bfloat162float(hy),
                           v.z - __bfloat162float(hz), v.w - __bfloat162float(hw));
    __nv_bfloat162 h01; h01.x = hx; h01.y = hy;
    __nv_bfloat162 h23; h23.x = hz; h23.y = hw;
    uint2 h; h.x = *(unsigned int*)&h01; h.y = *(unsigned int*)&h23;
    *hi = h;
    *lo = f4_to_bf8(r);
}

__global__ __launch_bounds__(256) void conv_wcat_kernel(
    const float* __restrict__ Wq, const float* __restrict__ Whh)
{
    int r = blockIdx.x;
    const float* src = (r < Hh) ? (Wq + (size_t)r * Hh) : (Whh + (size_t)(r - Hh) * Hh);
    int c = threadIdx.x * 4;
    float4 v = *(const float4*)(src + c);
    uint2 hi, lo;
    split_f4(v, &hi, &lo);
    *(uint2*)(g_Wcat_hi + (size_t)r * Hh + c) = hi;
    *(uint2*)(g_Wcat_lo + (size_t)r * Hh + c) = lo;
}

__global__ __launch_bounds__(256) void conv_wc_kernel(const float* __restrict__ Wih)
{
    int rp = blockIdx.x;
    int jl = rp & 7;
    int q = rp >> 3;
    int g = q % 3;
    int jg = q / 3;
    int j = jg * 8 + jl;
    const float* src = Wih + (size_t)(g * Hh + j) * (2 * Hh) + Hh;
    int c = threadIdx.x * 4;
    float4 v = *(const float4*)(src + c);
    uint2 hi, lo;
    split_f4(v, &hi, &lo);
    *(uint2*)(g_Wc_hi + (size_t)rp * Hh + c) = hi;
    *(uint2*)(g_Wc_lo + (size_t)rp * Hh + c) = lo;
}

__global__ __launch_bounds__(256) void gather_emb_kernel(
    const float* __restrict__ emb, const int* __restrict__ tgt)
{
    int r = blockIdx.x;
    int t = r >> 4, b = r & 15;
    int tok = (t == 0) ? BOSTOK : tgt[b * Tt + (t - 1)];
    int c = threadIdx.x * 4;
    float4 v = *(const float4*)(emb + (size_t)tok * Hh + c);
    *(uint2*)(g_embbf + (size_t)r * Hh + c) = f4_to_bf8(v);
}

// ---------------- h0 init (also resets grid barrier) / hT copy ----------------
__global__ void init_h_kernel(const float* __restrict__ h0) {
    int i = blockIdx.x * 256 + threadIdx.x;
    if (i == 0) g_barcnt = 0;
    if (i < Bb * Hh) {
        float v = h0[i];
        g_H[i] = v;
        __nv_bfloat16 hi = __float2bfloat16(v);
        g_hhi[i] = hi;
        g_hlo[i] = __float2bfloat16(v - __bfloat162float(hi));
    }
}
__global__ void copy_hT_kernel(float* __restrict__ dst) {
    int i = blockIdx.x * 256 + threadIdx.x;
    if (i < Bb * Hh) dst[i] = g_H[(size_t)Tt * Bb * Hh + i];
}

// ---------------- mma primitive ----------------
__device__ __forceinline__ void mma16816(float* c, unsigned int a0, unsigned int a1,
                                         unsigned int a2, unsigned int a3,
                                         unsigned int b0, unsigned int b1)
{
    asm volatile(
        "mma.sync.aligned.m16n8k16.row.col.f32.bf16.bf16.f32 "
        "{%0,%1,%2,%3}, {%4,%5,%6,%7}, {%8,%9}, {%0,%1,%2,%3};\n"
        : "+f"(c[0]), "+f"(c[1]), "+f"(c[2]), "+f"(c[3])
        : "r"(a0), "r"(a1), "r"(a2), "r"(a3), "r"(b0), "r"(b1));
}

// ---------------- big bf16 TC GEMM (gx_emb + logits), cp.async 2-stage -------
__global__ __launch_bounds__(256) void bf16_mma_kernel(
    const __nv_bfloat16* __restrict__ A, const __nv_bfloat16* __restrict__ Bm,
    const float* __restrict__ bias, float* __restrict__ out, int N, int remap)
{
    __shared__ __align__(16) __nv_bfloat16 sA[2][128][40];
    __shared__ __align__(16) __nv_bfloat16 sB[2][64][40];

    const int tid = threadIdx.x;
    const int warp = tid >> 5;
    const int lane = tid & 31;
    const int wm = (warp & 3) * 32;
    const int wn = (warp >> 2) * 32;
    const int bm = blockIdx.y * 128;
    const int bn = blockIdx.x * 64;

    const int lr = tid >> 2;
    const int lc = (tid & 3) * 8;

    const __nv_bfloat16* Abase = A + (size_t)(bm + lr) * Hh + lc;
    const __nv_bfloat16* A2base = A + (size_t)(bm + lr + 64) * Hh + lc;
    const __nv_bfloat16* Bbase = Bm + (size_t)(bn + lr) * Hh + lc;

    float acc[2][4][4] = {};
    const int row = lane >> 2;
    const int kc = (lane & 3) * 2;

    auto issue = [&](int st, int k0) {
        CPA16(smem_u32p(&sA[st][lr][lc]), Abase + k0);
        CPA16(smem_u32p(&sA[st][lr + 64][lc]), A2base + k0);
        CPA16(smem_u32p(&sB[st][lr][lc]), Bbase + k0);
        CPA_COMMIT();
    };

    issue(0, 0);
    for (int k = 0; k < 32; k++) {
        const int st = k & 1;
        if (k + 1 < 32) { issue(st ^ 1, (k + 1) * 32); CPA_WAIT(1); }
        else            { CPA_WAIT(0); }
        __syncthreads();
#pragma unroll
        for (int kk = 0; kk < 32; kk += 16) {
            unsigned int a[2][4], b[4][2];
#pragma unroll
            for (int mf = 0; mf < 2; mf++) {
                int r0 = wm + mf * 16 + row;
                a[mf][0] = *(const unsigned int*)&sA[st][r0][kk + kc];
                a[mf][1] = *(const unsigned int*)&sA[st][r0 + 8][kk + kc];
                a[mf][2] = *(const unsigned int*)&sA[st][r0][kk + kc + 8];
                a[mf][3] = *(const unsigned int*)&sA[st][r0 + 8][kk + kc + 8];
            }
#pragma unroll
            for (int nf = 0; nf < 4; nf++) {
                int r0 = wn + nf * 8 + row;
                b[nf][0] = *(const unsigned int*)&sB[st][r0][kk + kc];
                b[nf][1] = *(const unsigned int*)&sB[st][r0][kk + kc + 8];
            }
#pragma unroll
            for (int mf = 0; mf < 2; mf++)
#pragma unroll
                for (int nf = 0; nf < 4; nf++)
                    mma16816(acc[mf][nf], a[mf][0], a[mf][1], a[mf][2], a[mf][3],
                             b[nf][0], b[nf][1]);
        }
        __syncthreads();
    }

#pragma unroll
    for (int mf = 0; mf < 2; mf++) {
#pragma unroll
        for (int nf = 0; nf < 4; nf++) {
            int gm = bm + wm + mf * 16 + row;
            int gn = bn + wn + nf * 8 + kc;
            float bi0 = bias[gn], bi1 = bias[gn + 1];
            int o0 = remap ? ((gm & 15) * Tt + (gm >> 4)) : gm;
            *(float2*)(out + (size_t)o0 * N + gn) =
                make_float2(acc[mf][nf][0] + bi0, acc[mf][nf][1] + bi1);
            int gm2 = gm + 8;
            int o1 = remap ? ((gm2 & 15) * Tt + (gm2 >> 4)) : gm2;
            *(float2*)(out + (size_t)o1 * N + gn) =
                make_float2(acc[mf][nf][2] + bi0, acc[mf][nf][3] + bi1);
        }
    }
}

// ---------------- persistent decode loop: 128 blocks x 256 threads -----------
struct SmemA { __nv_bfloat16 Ah[2][16][40], Al[2][16][40], Bh[2][64][40], Bl[2][64][40]; };
struct SmemB { float q[Hh]; float v[Hh]; };
struct SmemC { float w[Ss]; float sred[4]; float sred2[4]; };
struct SmemD { __nv_bfloat16 Ah[2][16][40], Al[2][16][40], Bh[2][48][40], Bl[2][48][40];
               float sgx[2][3][8][16]; };

__global__ __launch_bounds__(256) void loop_kernel(
    const float* __restrict__ enc, const float* __restrict__ vat,
    const float* __restrict__ bhh, float* __restrict__ attw)
{
    __shared__ __align__(16) unsigned char sraw[25600];

    const int g = blockIdx.x;
    const int tid = threadIdx.x;
    const int warp = tid >> 5;
    const int lane = tid & 31;
    const int row = lane >> 2;
    const int kc = (lane & 3) * 2;
    const int lr = tid >> 2;
    const int lc = (tid & 3) * 8;
    const int lrA = (tid & 63) >> 2;
    const int wn = warp * 8;
    unsigned bo = 0;

    // stage A fixed addressing
    const int ntA = g & 63, ksA = g >> 6;
    const int bnA = ntA * 64, kbA = ksA * 512;
    const __nv_bfloat16* gBhA = g_Wcat_hi + (size_t)(bnA + lr) * Hh + kbA + lc;
    const __nv_bfloat16* gBlA = g_Wcat_lo + (size_t)(bnA + lr) * Hh + kbA + lc;
    const __nv_bfloat16* gAA =
        (tid < 64)  ? g_hhi + (size_t)lrA * Hh + kbA + lc :
        (tid < 128) ? g_hlo + (size_t)lrA * Hh + kbA + lc : g_hhi;

    // stage B / C fixed addressing
    const int bB = g >> 3, sbB = (g & 7) * 16;
    const int bC = g >> 3, hcC = g & 7;

    // stage D fixed addressing (valid for g < 64, tid < 192)
    const int bnD = (g & 63) * 48;
    const __nv_bfloat16* gBhD = g_Wc_hi + (size_t)(bnD + lr) * Hh + lc;
    const __nv_bfloat16* gBlD = g_Wc_lo + (size_t)(bnD + lr) * Hh + lc;
    const __nv_bfloat16* gAD =
        (tid < 64)  ? g_chi + (size_t)lrA * Hh + lc :
        (tid < 128) ? g_clo + (size_t)lrA * Hh + lc : g_chi;

    for (int t = 0; t < Tt; t++) {
        // ================= stage A: [q | gh] partials (K-split 2) =============
        {
            SmemA& sa = *reinterpret_cast<SmemA*>(sraw);
            float c0[4] = {}, c1[4] = {}, c2[4] = {};
            {
                if (tid < 64)       CPA16CG(smem_u32p(&sa.Ah[0][lrA][lc]), gAA);
                else if (tid < 128) CPA16CG(smem_u32p(&sa.Al[0][lrA][lc]), gAA);
                CPA16(smem_u32p(&sa.Bh[0][lr][lc]), gBhA);
                CPA16(smem_u32p(&sa.Bl[0][lr][lc]), gBlA);
                CPA_COMMIT();
            }
            for (int k = 0; k < 16; k++) {
                const int st = k & 1;
                if (k + 1 < 16) {
                    const int k0 = (k + 1) * 32;
                    if (tid < 64)       CPA16CG(smem_u32p(&sa.Ah[st ^ 1][lrA][lc]), gAA + k0);
                    else if (tid < 128) CPA16CG(smem_u32p(&sa.Al[st ^ 1][lrA][lc]), gAA + k0);
                    CPA16(smem_u32p(&sa.Bh[st ^ 1][lr][lc]), gBhA + k0);
                    CPA16(smem_u32p(&sa.Bl[st ^ 1][lr][lc]), gBlA + k0);
                    CPA_COMMIT();
                    CPA_WAIT(1);
                } else CPA_WAIT(0);
                __syncthreads();
#pragma unroll
                for (int kk = 0; kk < 32; kk += 16) {
                    unsigned int ah0 = *(const unsigned int*)&sa.Ah[st][row][kk + kc];
                    unsigned int ah1 = *(const unsigned int*)&sa.Ah[st][row + 8][kk + kc];
                    unsigned int ah2 = *(const unsigned int*)&sa.Ah[st][row][kk + kc + 8];
                    unsigned int ah3 = *(const unsigned int*)&sa.Ah[st][row + 8][kk + kc + 8];
                    unsigned int al0 = *(const unsigned int*)&sa.Al[st][row][kk + kc];
                    unsigned int al1 = *(const unsigned int*)&sa.Al[st][row + 8][kk + kc];
                    unsigned int al2 = *(const unsigned int*)&sa.Al[st][row][kk + kc + 8];
                    unsigned int al3 = *(const unsigned int*)&sa.Al[st][row + 8][kk + kc + 8];
                    unsigned int bh0 = *(const unsigned int*)&sa.Bh[st][wn + row][kk + kc];
                    unsigned int bh1 = *(const unsigned int*)&sa.Bh[st][wn + row][kk + kc + 8];
                    unsigned int bl0 = *(const unsigned int*)&sa.Bl[st][wn + row][kk + kc];
                    unsigned int bl1 = *(const unsigned int*)&sa.Bl[st][wn + row][kk + kc + 8];
                    mma16816(c0, ah0, ah1, ah2, ah3, bh0, bh1);
                    mma16816(c1, ah0, ah1, ah2, ah3, bl0, bl1);
                    mma16816(c2, al0, al1, al2, al3, bh0, bh1);
                }
                __syncthreads();
            }
            float v0 = c0[0] + c1[0] + c2[0];
            float v1 = c0[1] + c1[1] + c2[1];
            float v2 = c0[2] + c1[2] + c2[2];
            float v3 = c0[3] + c1[3] + c2[3];
            int gn = bnA + wn + kc;
            if (gn < Hh) {
                float* qd = g_q2[ksA];
                *(float2*)(qd + (size_t)row * Hh + gn)       = make_float2(v0, v1);
                *(float2*)(qd + (size_t)(row + 8) * Hh + gn) = make_float2(v2, v3);
            } else {
                int n = gn - Hh;
                float* gd = g_gh2[ksA];
                *(float2*)(gd + (size_t)row * 3 * Hh + n)       = make_float2(v0, v1);
                *(float2*)(gd + (size_t)(row + 8) * 3 * Hh + n) = make_float2(v2, v3);
            }
        }
        gbar(bo);

        // ================= stage B: scores ====================================
        {
            SmemB& sb = *reinterpret_cast<SmemB*>(sraw);
            float4 q0 = __ldcg((const float4*)g_q2[0] + bB * 256 + tid);
            float4 q1 = __ldcg((const float4*)g_q2[1] + bB * 256 + tid);
            ((float4*)sb.q)[tid] = make_float4(q0.x + q1.x, q0.y + q1.y,
                                               q0.z + q1.z, q0.w + q1.w);
            ((float4*)sb.v)[tid] = __ldg((const float4*)vat + tid);
            __syncthreads();
#pragma unroll
            for (int si = 0; si < 2; si++) {
                int s = sbB + warp * 2 + si;
                const float4* kp = (const float4*)(g_kproj + (size_t)(bB * Ss + s) * Hh);
                float acc = 0.f;
#pragma unroll
                for (int i = 0; i < 8; i++) {
                    int idx = i * 32 + lane;
                    float4 k4 = __ldg(kp + idx);
                    float4 q4 = ((const float4*)sb.q)[idx];
                    float4 v4 = ((const float4*)sb.v)[idx];
                    acc = fmaf(v4.x, tanh_approx(q4.x + k4.x), acc);
                    acc = fmaf(v4.y, tanh_approx(q4.y + k4.y), acc);
                    acc = fmaf(v4.z, tanh_approx(q4.z + k4.z), acc);
                    acc = fmaf(v4.w, tanh_approx(q4.w + k4.w), acc);
                }
#pragma unroll
                for (int o = 16; o; o >>= 1) acc += __shfl_xor_sync(~0u, acc, o);
                if (lane == 0) g_scores[bB * Ss + s] = acc;
            }
        }
        gbar(bo);

        // ================= stage C: softmax + ctx =============================
        {
            SmemC& sc = *reinterpret_cast<SmemC*>(sraw);
            float sval = 0.f;
            if (tid < 128) {
                sval = __ldcg(g_scores + bC * Ss + tid);
                float mx = sval;
#pragma unroll
                for (int o = 16; o; o >>= 1) mx = fmaxf(mx, __shfl_xor_sync(~0u, mx, o));
                if ((tid & 31) == 0) sc.sred[tid >> 5] = mx;
            }
            __syncthreads();
            float mxx = fmaxf(fmaxf(sc.sred[0], sc.sred[1]), fmaxf(sc.sred[2], sc.sred[3]));
            float e = 0.f;
            if (tid < 128) {
                e = __expf(sval - mxx);
                float sm = e;
#pragma unroll
                for (int o = 16; o; o >>= 1) sm += __shfl_xor_sync(~0u, sm, o);
                if ((tid & 31) == 0) sc.sred2[tid >> 5] = sm;
            }
            __syncthreads();
            float tot = sc.sred2[0] + sc.sred2[1] + sc.sred2[2] + sc.sred2[3];
            if (tid < 128) {
                float wv = __fdividef(e, tot);
                sc.w[tid] = wv;
                if (hcC == 0) attw[((size_t)bC * Tt + t) * Ss + tid] = wv;
            }
            __syncthreads();
            if (tid < 128) {
                int h = hcC * 128 + tid;
                const float* ep = enc + ((size_t)bC * Ss) * Hh + h;
                float acc = 0.f;
#pragma unroll 8
                for (int s = 0; s < Ss; s++) acc = fmaf(sc.w[s], ep[(size_t)s * Hh], acc);
                __nv_bfloat16 hi = __float2bfloat16(acc);
                g_chi[bC * Hh + h] = hi;
                g_clo[bC * Hh + h] = __float2bfloat16(acc - __bfloat162float(hi));
            }
        }
        gbar(bo);

        // ================= stage D: gx_ctx GEMM + fused gate update ===========
        if (g < 64) {
            SmemD& sd = *reinterpret_cast<SmemD*>(sraw);
            float c0[4] = {}, c1[4] = {}, c2[4] = {};
            if (tid < 192) {
                if (tid < 64)       CPA16CG(smem_u32p(&sd.Ah[0][lrA][lc]), gAD);
                else if (tid < 128) CPA16CG(smem_u32p(&sd.Al[0][lrA][lc]), gAD);
                CPA16(smem_u32p(&sd.Bh[0][lr][lc]), gBhD);
                CPA16(smem_u32p(&sd.Bl[0][lr][lc]), gBlD);
                CPA_COMMIT();
            }
            for (int k = 0; k < 32; k++) {
                const int st = k & 1;
                if (tid < 192) {
                    if (k + 1 < 32) {
                        const int k0 = (k + 1) * 32;
                        if (tid < 64)       CPA16CG(smem_u32p(&sd.Ah[st ^ 1][lrA][lc]), gAD + k0);
                        else if (tid < 128) CPA16CG(smem_u32p(&sd.Al[st ^ 1][lrA][lc]), gAD + k0);
                        CPA16(smem_u32p(&sd.Bh[st ^ 1][lr][lc]), gBhD + k0);
                        CPA16(smem_u32p(&sd.Bl[st ^ 1][lr][lc]), gBlD + k0);
                        CPA_COMMIT();
                        CPA_WAIT(1);
                    } else CPA_WAIT(0);
                }
                __syncthreads();
                if (tid < 192) {
#pragma unroll
                    for (int kk = 0; kk < 32; kk += 16) {
                        unsigned int ah0 = *(const unsigned int*)&sd.Ah[st][row][kk + kc];
                        unsigned int ah1 = *(const unsigned int*)&sd.Ah[st][row + 8][kk + kc];
                        unsigned int ah2 = *(const unsigned int*)&sd.Ah[st][row][kk + kc + 8];
                        unsigned int ah3 = *(const unsigned int*)&sd.Ah[st][row + 8][kk + kc + 8];
                        unsigned int al0 = *(const unsigned int*)&sd.Al[st][row][kk + kc];
                        unsigned int al1 = *(const unsigned int*)&sd.Al[st][row + 8][kk + kc];
                        unsigned int al2 = *(const unsigned int*)&sd.Al[st][row][kk + kc + 8];
                        unsigned int al3 = *(const unsigned int*)&sd.Al[st][row + 8][kk + kc + 8];
                        unsigned int bh0 = *(const unsigned int*)&sd.Bh[st][wn + row][kk + kc];
                        unsigned int bh1 = *(const unsigned int*)&sd.Bh[st][wn + row][kk + kc + 8];
                        unsigned int bl0 = *(const unsigned int*)&sd.Bl[st][wn + row][kk + kc];
                        unsigned int bl1 = *(const unsigned int*)&sd.Bl[st][wn + row][kk + kc + 8];
                        mma16816(c0, ah0, ah1, ah2, ah3, bh0, bh1);
                        mma16816(c1, ah0, ah1, ah2, ah3, bl0, bl1);
                        mma16816(c2, al0, al1, al2, al3, bh0, bh1);
                    }
                }
                __syncthreads();
            }
            if (tid < 192) {
                int gg = warp % 3, jgl = warp / 3;
                sd.sgx[jgl][gg][kc][row]         = c0[0] + c1[0] + c2[0];
                sd.sgx[jgl][gg][kc + 1][row]     = c0[1] + c1[1] + c2[1];
                sd.sgx[jgl][gg][kc][row + 8]     = c0[2] + c1[2] + c2[2];
                sd.sgx[jgl][gg][kc + 1][row + 8] = c0[3] + c1[3] + c2[3];
            }
            __syncthreads();
            {
                const float* hprev = g_H + (size_t)t * Bb * Hh;
                float* hnew = g_H + (size_t)(t + 1) * Bb * Hh;
                int m = tid & 15;
                int jloc = tid >> 4;
                int jgl = jloc >> 3, jl = jloc & 7;
                int j = (g & 63) * 16 + jloc;
                int r = t * Bb + m;
                const float* gxe = g_gxemb + (size_t)r * 3 * Hh;
                const float* g0 = g_gh2[0] + (size_t)m * 3 * Hh;
                const float* g1 = g_gh2[1] + (size_t)m * 3 * Hh;
                float gx_r = sd.sgx[jgl][0][jl][m] + gxe[j];
                float gx_z = sd.sgx[jgl][1][jl][m] + gxe[Hh + j];
                float gx_n = sd.sgx[jgl][2][jl][m] + gxe[2 * Hh + j];
                float gh_r = __ldcg(g0 + j)          + __ldcg(g1 + j)          + bhh[j];
                float gh_z = __ldcg(g0 + Hh + j)     + __ldcg(g1 + Hh + j)     + bhh[Hh + j];
                float gh_n = __ldcg(g0 + 2 * Hh + j) + __ldcg(g1 + 2 * Hh + j) + bhh[2 * Hh + j];
                float rg = fast_sigmoid(gx_r + gh_r);
                float z  = fast_sigmoid(gx_z + gh_z);
                float nn = fast_tanh(gx_n + rg * gh_n);
                float hp = hprev[m * Hh + j];
                float hv = (1.f - z) * nn + z * hp;
                hnew[m * Hh + j] = hv;
                g_Hbf[(size_t)r * Hh + j] = __float2bfloat16(hv);
                __nv_bfloat16 hi = __float2bfloat16(hv);
                g_hhi[m * Hh + j] = hi;
                g_hlo[m * Hh + j] = __float2bfloat16(hv - __bfloat162float(hi));
            }
        }
        gbar(bo);
    }
}

// ---------------- final: in-place log_softmax over V per (b,t) row -----------
__global__ __launch_bounds__(256) void logsoftmax_kernel(float* __restrict__ out)
{
    float* row = out + (size_t)blockIdx.x * Vv;
    int tid = threadIdx.x;
    __shared__ float sred[8];

    float mx = -FLT_MAX;
    for (int v = tid; v < Vv; v += 256) mx = fmaxf(mx, row[v]);
#pragma unroll
    for (int o = 16; o; o >>= 1) mx = fmaxf(mx, __shfl_xor_sync(~0u, mx, o));
    if ((tid & 31) == 0) sred[tid >> 5] = mx;
    __syncthreads();
    mx = sred[0];
#pragma unroll
    for (int i = 1; i < 8; i++) mx = fmaxf(mx, sred[i]);

    float s = 0.f;
    for (int v = tid; v < Vv; v += 256) s += __expf(row[v] - mx);
#pragma unroll
    for (int o = 16; o; o >>= 1) s += __shfl_xor_sync(~0u, s, o);
    __syncthreads();
    if ((tid & 31) == 0) sred[tid >> 5] = s;
    __syncthreads();
    s = sred[0] + sred[1] + sred[2] + sred[3] + sred[4] + sred[5] + sred[6] + sred[7];

    float lse = mx + logf(s);
    for (int v = tid; v < Vv; v += 256) row[v] -= lse;
}

// ---------------- orchestration ----------------
extern "C" void kernel_launch(void* const* d_in, const int* in_sizes, int n_in,
                              void* d_out, int out_size)
{
    const float* enc  = (const float*)d_in[0];
    const float* h0   = (const float*)d_in[1];
    const int*   tgt  = (const int*)  d_in[2];
    const float* emb  = (const float*)d_in[3];
    const float* Wq   = (const float*)d_in[4];
    const float* Wk   = (const float*)d_in[5];
    const float* vat  = (const float*)d_in[6];
    const float* Wih  = (const float*)d_in[7];
    const float* Whh  = (const float*)d_in[8];
    const float* bih  = (const float*)d_in[9];
    const float* bhh  = (const float*)d_in[10];
    const float* Wout = (const float*)d_in[11];
    const float* bout = (const float*)d_in[12];

    float* out       = (float*)d_out;
    float* out_hT    = out + (size_t)Bb * Tt * Vv;
    float* out_attw  = out_hT + (size_t)Bb * Hh;

    (void)in_sizes; (void)n_in; (void)out_size;

    // Phase 0: one-time conversions / precomputes
    conv_wout_kernel<<<4096, 256>>>(Wout);
    conv_wihemb_kernel<<<3 * Hh, 256>>>(Wih);
    conv_wcat_kernel<<<4 * Hh, 256>>>(Wq, Whh);
    conv_wc_kernel<<<3 * Hh, 256>>>(Wih);
    gather_emb_kernel<<<Tt * Bb, 256>>>(emb, tgt);
    {
        __nv_bfloat16 *Abf, *Bbf;
        float* gxemb_ptr;
        cudaGetSymbolAddress((void**)&Abf, g_embbf);
        cudaGetSymbolAddress((void**)&Bbf, g_Wihembbf);
        cudaGetSymbolAddress((void**)&gxemb_ptr, g_gxemb);
        bf16_mma_kernel<<<dim3(3 * Hh / 64, (Tt * Bb) / 128), 256>>>(
            Abf, Bbf, bih, gxemb_ptr, 3 * Hh, 0);
    }
    gemm_tn_kernel<<<dim3(Hh / 64, (Bb * Ss) / 64), 256>>>(enc, Wk, Hh);
    init_h_kernel<<<(Bb * Hh + 255) / 256, 256>>>(h0);

    // Phase 2: entire sequential decode in ONE persistent kernel
    loop_kernel<<<GRIDB, 256>>>(enc, vat, bhh, out_attw);

    copy_hT_kernel<<<(Bb * Hh + 255) / 256, 256>>>(out_hT);

    // Phase 3: logits on tensor cores + log_softmax
    {
        __nv_bfloat16 *Abf, *Bbf;
        cudaGetSymbolAddress((void**)&Abf, g_Hbf);
        cudaGetSymbolAddress((void**)&Bbf, g_Woutbf);
        bf16_mma_kernel<<<dim3(Vv / 64, (Tt * Bb) / 128), 256>>>(
            Abf, Bbf, bout, out, Vv, 1);
    }
    logsoftmax_kernel<<<Bb * Tt, 256>>>(out);
}

// round 7
// speedup vs baseline: 1.9561x; 1.2416x over previous
#include <cuda_runtime.h>
#include <cuda_bf16.h>
#include <math.h>
#include <float.h>

#define Bb 16
#define Ss 128
#define Tt 128
#define Hh 1024
#define Vv 32000
#define BOSTOK 1
#define GRIDB 128u

// ---------------- scratch (device globals; no allocs allowed) ----------------
__device__ float g_kproj[Bb * Ss * Hh];
__device__ float g_H[(Tt + 1) * Bb * Hh];
__device__ __nv_bfloat16 g_Hbf[Tt * Bb * Hh];
__device__ __nv_bfloat16 g_Woutbf[(size_t)Vv * Hh];
__device__ __nv_bfloat16 g_embbf[Tt * Bb * Hh];
__device__ __nv_bfloat16 g_Wihembbf[3 * Hh * Hh];
__device__ float g_gxemb[Tt * Bb * 3 * Hh];
__device__ __nv_bfloat16 g_Wcat_hi[4 * Hh * Hh];
__device__ __nv_bfloat16 g_Wcat_lo[4 * Hh * Hh];
__device__ __nv_bfloat16 g_Wc_hi[3 * Hh * Hh];
__device__ __nv_bfloat16 g_Wc_lo[3 * Hh * Hh];
__device__ __nv_bfloat16 g_hhi[Bb * Hh], g_hlo[Bb * Hh];
__device__ __nv_bfloat16 g_chi[Bb * Hh], g_clo[Bb * Hh];
__device__ float g_q2[2][Bb * Hh];
__device__ float g_gh2[2][Bb * 3 * Hh];
__device__ float g_scores[Bb * Ss];
__device__ unsigned g_barcnt;

// ---------------- math helpers ----------------
__device__ __forceinline__ float fast_tanh(float x) {
    float xc = fminf(fmaxf(x, -15.f), 15.f);
    float t = __expf(2.f * xc);
    return __fdividef(t - 1.f, t + 1.f);
}
__device__ __forceinline__ float fast_sigmoid(float x) {
    return __fdividef(1.f, 1.f + __expf(-x));
}
__device__ __forceinline__ float tanh_approx(float x) {
    float y;
    asm("tanh.approx.f32 %0, %1;" : "=f"(y) : "f"(x));
    return y;
}
__device__ __forceinline__ uint2 f4_to_bf8(float4 v) {
    __nv_bfloat162 lo = __floats2bfloat162_rn(v.x, v.y);
    __nv_bfloat162 hi = __floats2bfloat162_rn(v.z, v.w);
    uint2 o;
    o.x = *(const unsigned int*)&lo;
    o.y = *(const unsigned int*)&hi;
    return o;
}

// ---------------- cp.async helpers ----------------
__device__ __forceinline__ unsigned int smem_u32p(const void* p) {
    return (unsigned int)__cvta_generic_to_shared(p);
}
#define CPA16(dst_u32, src_ptr) \
    asm volatile("cp.async.ca.shared.global [%0], [%1], 16;" :: "r"(dst_u32), "l"(src_ptr))
#define CPA16CG(dst_u32, src_ptr) \
    asm volatile("cp.async.cg.shared.global [%0], [%1], 16;" :: "r"(dst_u32), "l"(src_ptr))
#define CPA_COMMIT() asm volatile("cp.async.commit_group;")
#define CPA_WAIT(n)  asm volatile("cp.async.wait_group %0;" :: "n"(n))

// ---------------- software grid barrier (all GRIDB blocks resident) ----------
__device__ __forceinline__ void gbar(unsigned& bo) {
    bo += GRIDB;
    __syncthreads();
    if (threadIdx.x == 0) {
        __threadfence();
        atomicAdd(&g_barcnt, 1u);
        while (*((volatile unsigned*)&g_barcnt) < bo) { }
        __threadfence();
    }
    __syncthreads();
}

// ---------------- fp32 GEMM for kproj ----------------
__global__ __launch_bounds__(256) void gemm_tn_kernel(
    const float* __restrict__ A, const float* __restrict__ Bw, int K)
{
    __shared__ float sA[16][64];
    __shared__ float sB[16][64];
    const int tid = threadIdx.x;
    const int bm = blockIdx.y * 64;
    const int bn = blockIdx.x * 64;
    const int lrow = tid >> 2;
    const int lk = (tid & 3) << 2;
    const int tx = tid & 15;
    const int ty = tid >> 4;

    const float* Ap = A + (size_t)(bm + lrow) * K + lk;
    const float* Bp = Bw + (size_t)(bn + lrow) * K + lk;

    float acc[4][4] = {};
    for (int k0 = 0; k0 < K; k0 += 16) {
        float4 av = *(const float4*)(Ap + k0);
        float4 bv = *(const float4*)(Bp + k0);
        sA[lk + 0][lrow] = av.x; sA[lk + 1][lrow] = av.y;
        sA[lk + 2][lrow] = av.z; sA[lk + 3][lrow] = av.w;
        sB[lk + 0][lrow] = bv.x; sB[lk + 1][lrow] = bv.y;
        sB[lk + 2][lrow] = bv.z; sB[lk + 3][lrow] = bv.w;
        __syncthreads();
#pragma unroll
        for (int kk = 0; kk < 16; kk++) {
            float4 a = *(const float4*)&sA[kk][ty << 2];
            float4 b = *(const float4*)&sB[kk][tx << 2];
            acc[0][0] = fmaf(a.x, b.x, acc[0][0]); acc[0][1] = fmaf(a.x, b.y, acc[0][1]);
            acc[0][2] = fmaf(a.x, b.z, acc[0][2]); acc[0][3] = fmaf(a.x, b.w, acc[0][3]);
            acc[1][0] = fmaf(a.y, b.x, acc[1][0]); acc[1][1] = fmaf(a.y, b.y, acc[1][1]);
            acc[1][2] = fmaf(a.y, b.z, acc[1][2]); acc[1][3] = fmaf(a.y, b.w, acc[1][3]);
            acc[2][0] = fmaf(a.z, b.x, acc[2][0]); acc[2][1] = fmaf(a.z, b.y, acc[2][1]);
            acc[2][2] = fmaf(a.z, b.z, acc[2][2]); acc[2][3] = fmaf(a.z, b.w, acc[2][3]);
            acc[3][0] = fmaf(a.w, b.x, acc[3][0]); acc[3][1] = fmaf(a.w, b.y, acc[3][1]);
            acc[3][2] = fmaf(a.w, b.z, acc[3][2]); acc[3][3] = fmaf(a.w, b.w, acc[3][3]);
        }
        __syncthreads();
    }
#pragma unroll
    for (int i = 0; i < 4; i++) {
        int m = bm + (ty << 2) + i;
        int n = bn + (tx << 2);
        *(float4*)(g_kproj + (size_t)m * Hh + n) =
            make_float4(acc[i][0], acc[i][1], acc[i][2], acc[i][3]);
    }
}

// ---------------- one-time conversions / gathers ----------------
__global__ __launch_bounds__(256) void conv_wout_kernel(const float* __restrict__ W)
{
    size_t n4 = (size_t)Vv * Hh / 4;
    uint2* dst = (uint2*)g_Woutbf;
    const float4* src = (const float4*)W;
    for (size_t i = blockIdx.x * 256 + threadIdx.x; i < n4; i += (size_t)gridDim.x * 256)
        dst[i] = f4_to_bf8(src[i]);
}

__global__ __launch_bounds__(256) void conv_wihemb_kernel(const float* __restrict__ Wih)
{
    int j = blockIdx.x;
    int c = threadIdx.x * 4;
    float4 v = *(const float4*)(Wih + (size_t)j * (2 * Hh) + c);
    *(uint2*)(g_Wihembbf + (size_t)j * Hh + c) = f4_to_bf8(v);
}

__device__ __forceinline__ void split_f4(float4 v, uint2* hi, uint2* lo)
{
    __nv_bfloat16 hx = __float2bfloat16(v.x), hy = __float2bfloat16(v.y);
    __nv_bfloat16 hz = __float2bfloat16(v.z), hw = __float2bfloat16(v.w);
    float4 r = make_float4(v.x - __bfloat162float(hx), v.y - __bfloat162float(hy),
                           v.z - __bfloat162float(hz), v.w - __bfloat162float(hw));
    __nv_bfloat162 h01; h01.x = hx; h01.y = hy;
    __nv_bfloat162 h23; h23.x = hz; h23.y = hw;
    uint2 h; h.x = *(unsigned int*)&h01; h.y = *(unsigned int*)&h23;
    *hi = h;
    *lo = f4_to_bf8(r);
}

__global__ __launch_bounds__(256) void conv_wcat_kernel(
    const float* __restrict__ Wq, const float* __restrict__ Whh)
{
    int r = blockIdx.x;
    const float* src = (r < Hh) ? (Wq + (size_t)r * Hh) : (Whh + (size_t)(r - Hh) * Hh);
    int c = threadIdx.x * 4;
    float4 v = *(const float4*)(src + c);
    uint2 hi, lo;
    split_f4(v, &hi, &lo);
    *(uint2*)(g_Wcat_hi + (size_t)r * Hh + c) = hi;
    *(uint2*)(g_Wcat_lo + (size_t)r * Hh + c) = lo;
}

__global__ __launch_bounds__(256) void conv_wc_kernel(const float* __restrict__ Wih)
{
    int rp = blockIdx.x;
    int jl = rp & 7;
    int q = rp >> 3;
    int g = q % 3;
    int jg = q / 3;
    int j = jg * 8 + jl;
    const float* src = Wih + (size_t)(g * Hh + j) * (2 * Hh) + Hh;
    int c = threadIdx.x * 4;
    float4 v = *(const float4*)(src + c);
    uint2 hi, lo;
    split_f4(v, &hi, &lo);
    *(uint2*)(g_Wc_hi + (size_t)rp * Hh + c) = hi;
    *(uint2*)(g_Wc_lo + (size_t)rp * Hh + c) = lo;
}

__global__ __launch_bounds__(256) void gather_emb_kernel(
    const float* __restrict__ emb, const int* __restrict__ tgt)
{
    int r = blockIdx.x;
    int t = r >> 4, b = r & 15;
    int tok = (t == 0) ? BOSTOK : tgt[b * Tt + (t - 1)];
    int c = threadIdx.x * 4;
    float4 v = *(const float4*)(emb + (size_t)tok * Hh + c);
    *(uint2*)(g_embbf + (size_t)r * Hh + c) = f4_to_bf8(v);
}

// ---------------- h0 init (also resets grid barrier) / hT copy ----------------
__global__ void init_h_kernel(const float* __restrict__ h0) {
    int i = blockIdx.x * 256 + threadIdx.x;
    if (i == 0) g_barcnt = 0;
    if (i < Bb * Hh) {
        float v = h0[i];
        g_H[i] = v;
        __nv_bfloat16 hi = __float2bfloat16(v);
        g_hhi[i] = hi;
        g_hlo[i] = __float2bfloat16(v - __bfloat162float(hi));
    }
}
__global__ void copy_hT_kernel(float* __restrict__ dst) {
    int i = blockIdx.x * 256 + threadIdx.x;
    if (i < Bb * Hh) dst[i] = g_H[(size_t)Tt * Bb * Hh + i];
}

// ---------------- mma primitive ----------------
__device__ __forceinline__ void mma16816(float* c, unsigned int a0, unsigned int a1,
                                         unsigned int a2, unsigned int a3,
                                         unsigned int b0, unsigned int b1)
{
    asm volatile(
        "mma.sync.aligned.m16n8k16.row.col.f32.bf16.bf16.f32 "
        "{%0,%1,%2,%3}, {%4,%5,%6,%7}, {%8,%9}, {%0,%1,%2,%3};\n"
        : "+f"(c[0]), "+f"(c[1]), "+f"(c[2]), "+f"(c[3])
        : "r"(a0), "r"(a1), "r"(a2), "r"(a3), "r"(b0), "r"(b1));
}

// ---------------- big bf16 TC GEMM (gx_emb + logits), cp.async 2-stage -------
__global__ __launch_bounds__(256) void bf16_mma_kernel(
    const __nv_bfloat16* __restrict__ A, const __nv_bfloat16* __restrict__ Bm,
    const float* __restrict__ bias, float* __restrict__ out, int N, int remap)
{
    __shared__ __align__(16) __nv_bfloat16 sA[2][128][40];
    __shared__ __align__(16) __nv_bfloat16 sB[2][64][40];

    const int tid = threadIdx.x;
    const int warp = tid >> 5;
    const int lane = tid & 31;
    const int wm = (warp & 3) * 32;
    const int wn = (warp >> 2) * 32;
    const int bm = blockIdx.y * 128;
    const int bn = blockIdx.x * 64;

    const int lr = tid >> 2;
    const int lc = (tid & 3) * 8;

    const __nv_bfloat16* Abase = A + (size_t)(bm + lr) * Hh + lc;
    const __nv_bfloat16* A2base = A + (size_t)(bm + lr + 64) * Hh + lc;
    const __nv_bfloat16* Bbase = Bm + (size_t)(bn + lr) * Hh + lc;

    float acc[2][4][4] = {};
    const int row = lane >> 2;
    const int kc = (lane & 3) * 2;

    auto issue = [&](int st, int k0) {
        CPA16(smem_u32p(&sA[st][lr][lc]), Abase + k0);
        CPA16(smem_u32p(&sA[st][lr + 64][lc]), A2base + k0);
        CPA16(smem_u32p(&sB[st][lr][lc]), Bbase + k0);
        CPA_COMMIT();
    };

    issue(0, 0);
    for (int k = 0; k < 32; k++) {
        const int st = k & 1;
        if (k + 1 < 32) { issue(st ^ 1, (k + 1) * 32); CPA_WAIT(1); }
        else            { CPA_WAIT(0); }
        __syncthreads();
#pragma unroll
        for (int kk = 0; kk < 32; kk += 16) {
            unsigned int a[2][4], b[4][2];
#pragma unroll
            for (int mf = 0; mf < 2; mf++) {
                int r0 = wm + mf * 16 + row;
                a[mf][0] = *(const unsigned int*)&sA[st][r0][kk + kc];
                a[mf][1] = *(const unsigned int*)&sA[st][r0 + 8][kk + kc];
                a[mf][2] = *(const unsigned int*)&sA[st][r0][kk + kc + 8];
                a[mf][3] = *(const unsigned int*)&sA[st][r0 + 8][kk + kc + 8];
            }
#pragma unroll
            for (int nf = 0; nf < 4; nf++) {
                int r0 = wn + nf * 8 + row;
                b[nf][0] = *(const unsigned int*)&sB[st][r0][kk + kc];
                b[nf][1] = *(const unsigned int*)&sB[st][r0][kk + kc + 8];
            }
#pragma unroll
            for (int mf = 0; mf < 2; mf++)
#pragma unroll
                for (int nf = 0; nf < 4; nf++)
                    mma16816(acc[mf][nf], a[mf][0], a[mf][1], a[mf][2], a[mf][3],
                             b[nf][0], b[nf][1]);
        }
        __syncthreads();
    }

#pragma unroll
    for (int mf = 0; mf < 2; mf++) {
#pragma unroll
        for (int nf = 0; nf < 4; nf++) {
            int gm = bm + wm + mf * 16 + row;
            int gn = bn + wn + nf * 8 + kc;
            float bi0 = bias[gn], bi1 = bias[gn + 1];
            int o0 = remap ? ((gm & 15) * Tt + (gm >> 4)) : gm;
            *(float2*)(out + (size_t)o0 * N + gn) =
                make_float2(acc[mf][nf][0] + bi0, acc[mf][nf][1] + bi1);
            int gm2 = gm + 8;
            int o1 = remap ? ((gm2 & 15) * Tt + (gm2 >> 4)) : gm2;
            *(float2*)(out + (size_t)o1 * N + gn) =
                make_float2(acc[mf][nf][2] + bi0, acc[mf][nf][3] + bi1);
        }
    }
}

// ---------------- persistent decode loop: 128 blocks x 256 threads -----------
// K-chunk 64, 3-deep cp.async pipelines in stages A and D.
struct SmemA { __nv_bfloat16 Ah[3][16][72], Al[3][16][72], Bh[3][64][72], Bl[3][64][72]; };
struct SmemB { float q[Hh]; float v[Hh]; };
struct SmemC { float w[Ss]; float part[128]; float sred[4]; float sred2[4]; };
struct SmemD { __nv_bfloat16 Ah[3][16][72], Al[3][16][72], Bh[3][48][72], Bl[3][48][72];
               float sgx[2][3][8][16]; };
#define LOOP_SMEM 70656

__global__ __launch_bounds__(256) void loop_kernel(
    const float* __restrict__ enc, const float* __restrict__ vat,
    const float* __restrict__ bhh, float* __restrict__ attw)
{
    extern __shared__ __align__(16) unsigned char sraw[];

    const int g = blockIdx.x;
    const int tid = threadIdx.x;
    const int warp = tid >> 5;
    const int lane = tid & 31;
    const int row = lane >> 2;
    const int kc = (lane & 3) * 2;
    const int lrB = tid >> 2;            // 0..63 (B-tile row)
    const int lcB = (tid & 3) * 16;      // 0,16,32,48
    const int rA = (tid & 63) >> 2;      // 0..15 (A-tile row)
    const int cA = (tid & 3) * 16;
    const int wn = warp * 8;
    unsigned bo = 0;

    // stage A fixed addressing
    const int ntA = g & 63, ksA = g >> 6;
    const int bnA = ntA * 64, kbA = ksA * 512;
    const __nv_bfloat16* gBhA = g_Wcat_hi + (size_t)(bnA + lrB) * Hh + kbA + lcB;
    const __nv_bfloat16* gBlA = g_Wcat_lo + (size_t)(bnA + lrB) * Hh + kbA + lcB;
    const __nv_bfloat16* gAhA = g_hhi + (size_t)rA * Hh + kbA + cA;
    const __nv_bfloat16* gAlA = g_hlo + (size_t)rA * Hh + kbA + cA;

    // stage B / C fixed addressing
    const int bB = g >> 3, sbB = (g & 7) * 16;
    const int bC = g >> 3, hcC = g & 7;

    // stage D fixed addressing (g < 64 active; B rows need tid < 192)
    const int bnD = (g & 63) * 48;
    const __nv_bfloat16* gBhD = g_Wc_hi + (size_t)(bnD + lrB) * Hh + lcB;
    const __nv_bfloat16* gBlD = g_Wc_lo + (size_t)(bnD + lrB) * Hh + lcB;
    const __nv_bfloat16* gAhD = g_chi + (size_t)rA * Hh + cA;
    const __nv_bfloat16* gAlD = g_clo + (size_t)rA * Hh + cA;

    for (int t = 0; t < Tt; t++) {
        // ================= stage A: [q | gh] partials (K-split 2) =============
        {
            SmemA& sa = *reinterpret_cast<SmemA*>(sraw);
            float c0[4] = {}, c1[4] = {}, c2[4] = {};

            auto issueA = [&](int st, int k0) {
                if (tid < 64) {
                    CPA16CG(smem_u32p(&sa.Ah[st][rA][cA]),     gAhA + k0);
                    CPA16CG(smem_u32p(&sa.Ah[st][rA][cA + 8]), gAhA + k0 + 8);
                } else if (tid < 128) {
                    CPA16CG(smem_u32p(&sa.Al[st][rA][cA]),     gAlA + k0);
                    CPA16CG(smem_u32p(&sa.Al[st][rA][cA + 8]), gAlA + k0 + 8);
                }
                CPA16(smem_u32p(&sa.Bh[st][lrB][lcB]),     gBhA + k0);
                CPA16(smem_u32p(&sa.Bh[st][lrB][lcB + 8]), gBhA + k0 + 8);
                CPA16(smem_u32p(&sa.Bl[st][lrB][lcB]),     gBlA + k0);
                CPA16(smem_u32p(&sa.Bl[st][lrB][lcB + 8]), gBlA + k0 + 8);
                CPA_COMMIT();
            };

            issueA(0, 0);
            issueA(1, 64);
            for (int k = 0; k < 8; k++) {
                const int st = k % 3;
                if (k < 6) { issueA((k + 2) % 3, (k + 2) * 64); CPA_WAIT(2); }
                else if (k == 6) CPA_WAIT(1);
                else CPA_WAIT(0);
                __syncthreads();
#pragma unroll
                for (int kk = 0; kk < 64; kk += 16) {
                    unsigned int ah0 = *(const unsigned int*)&sa.Ah[st][row][kk + kc];
                    unsigned int ah1 = *(const unsigned int*)&sa.Ah[st][row + 8][kk + kc];
                    unsigned int ah2 = *(const unsigned int*)&sa.Ah[st][row][kk + kc + 8];
                    unsigned int ah3 = *(const unsigned int*)&sa.Ah[st][row + 8][kk + kc + 8];
                    unsigned int al0 = *(const unsigned int*)&sa.Al[st][row][kk + kc];
                    unsigned int al1 = *(const unsigned int*)&sa.Al[st][row + 8][kk + kc];
                    unsigned int al2 = *(const unsigned int*)&sa.Al[st][row][kk + kc + 8];
                    unsigned int al3 = *(const unsigned int*)&sa.Al[st][row + 8][kk + kc + 8];
                    unsigned int bh0 = *(const unsigned int*)&sa.Bh[st][wn + row][kk + kc];
                    unsigned int bh1 = *(const unsigned int*)&sa.Bh[st][wn + row][kk + kc + 8];
                    unsigned int bl0 = *(const unsigned int*)&sa.Bl[st][wn + row][kk + kc];
                    unsigned int bl1 = *(const unsigned int*)&sa.Bl[st][wn + row][kk + kc + 8];
                    mma16816(c0, ah0, ah1, ah2, ah3, bh0, bh1);
                    mma16816(c1, ah0, ah1, ah2, ah3, bl0, bl1);
                    mma16816(c2, al0, al1, al2, al3, bh0, bh1);
                }
                __syncthreads();
            }
            float v0 = c0[0] + c1[0] + c2[0];
            float v1 = c0[1] + c1[1] + c2[1];
            float v2 = c0[2] + c1[2] + c2[2];
            float v3 = c0[3] + c1[3] + c2[3];
            int gn = bnA + wn + kc;
            if (gn < Hh) {
                float* qd = g_q2[ksA];
                *(float2*)(qd + (size_t)row * Hh + gn)       = make_float2(v0, v1);
                *(float2*)(qd + (size_t)(row + 8) * Hh + gn) = make_float2(v2, v3);
            } else {
                int n = gn - Hh;
                float* gd = g_gh2[ksA];
                *(float2*)(gd + (size_t)row * 3 * Hh + n)       = make_float2(v0, v1);
                *(float2*)(gd + (size_t)(row + 8) * 3 * Hh + n) = make_float2(v2, v3);
            }
        }
        gbar(bo);

        // ================= stage B: scores (2 per warp, interleaved) ==========
        {
            SmemB& sb = *reinterpret_cast<SmemB*>(sraw);
            float4 q0 = __ldcg((const float4*)g_q2[0] + bB * 256 + tid);
            float4 q1 = __ldcg((const float4*)g_q2[1] + bB * 256 + tid);
            ((float4*)sb.q)[tid] = make_float4(q0.x + q1.x, q0.y + q1.y,
                                               q0.z + q1.z, q0.w + q1.w);
            ((float4*)sb.v)[tid] = __ldg((const float4*)vat + tid);
            __syncthreads();
            int s0 = sbB + warp * 2;
            const float4* kp0 = (const float4*)(g_kproj + (size_t)(bB * Ss + s0) * Hh);
            const float4* kp1 = kp0 + 256;
            float a0 = 0.f, a1 = 0.f;
#pragma unroll
            for (int i = 0; i < 8; i++) {
                int idx = i * 32 + lane;
                float4 ka = __ldg(kp0 + idx);
                float4 kb = __ldg(kp1 + idx);
                float4 q4 = ((const float4*)sb.q)[idx];
                float4 v4 = ((const float4*)sb.v)[idx];
                a0 = fmaf(v4.x, tanh_approx(q4.x + ka.x), a0);
                a1 = fmaf(v4.x, tanh_approx(q4.x + kb.x), a1);
                a0 = fmaf(v4.y, tanh_approx(q4.y + ka.y), a0);
                a1 = fmaf(v4.y, tanh_approx(q4.y + kb.y), a1);
                a0 = fmaf(v4.z, tanh_approx(q4.z + ka.z), a0);
                a1 = fmaf(v4.z, tanh_approx(q4.z + kb.z), a1);
                a0 = fmaf(v4.w, tanh_approx(q4.w + ka.w), a0);
                a1 = fmaf(v4.w, tanh_approx(q4.w + kb.w), a1);
            }
#pragma unroll
            for (int o = 16; o; o >>= 1) {
                a0 += __shfl_xor_sync(~0u, a0, o);
                a1 += __shfl_xor_sync(~0u, a1, o);
            }
            if (lane == 0) {
                g_scores[bB * Ss + s0] = a0;
                g_scores[bB * Ss + s0 + 1] = a1;
            }
        }
        gbar(bo);

        // ================= stage C: softmax + ctx (256 threads, s-split) ======
        {
            SmemC& sc = *reinterpret_cast<SmemC*>(sraw);
            float sval = 0.f;
            if (tid < 128) {
                sval = __ldcg(g_scores + bC * Ss + tid);
                float mx = sval;
#pragma unroll
                for (int o = 16; o; o >>= 1) mx = fmaxf(mx, __shfl_xor_sync(~0u, mx, o));
                if ((tid & 31) == 0) sc.sred[tid >> 5] = mx;
            }
            __syncthreads();
            float mxx = fmaxf(fmaxf(sc.sred[0], sc.sred[1]), fmaxf(sc.sred[2], sc.sred[3]));
            float e = 0.f;
            if (tid < 128) {
                e = __expf(sval - mxx);
                float sm = e;
#pragma unroll
                for (int o = 16; o; o >>= 1) sm += __shfl_xor_sync(~0u, sm, o);
                if ((tid & 31) == 0) sc.sred2[tid >> 5] = sm;
            }
            __syncthreads();
            float tot = sc.sred2[0] + sc.sred2[1] + sc.sred2[2] + sc.sred2[3];
            if (tid < 128) {
                float wv = __fdividef(e, tot);
                sc.w[tid] = wv;
                if (hcC == 0) attw[((size_t)bC * Tt + t) * Ss + tid] = wv;
            }
            __syncthreads();
            {
                int h = hcC * 128 + (tid & 127);
                int sh = (tid >> 7) * 64;
                const float* ep = enc + ((size_t)bC * Ss + sh) * Hh + h;
                const float* wp = sc.w + sh;
                float acc = 0.f;
#pragma unroll 16
                for (int s = 0; s < 64; s++) acc = fmaf(wp[s], ep[(size_t)s * Hh], acc);
                if (tid >= 128) sc.part[tid & 127] = acc;
                __syncthreads();
                if (tid < 128) {
                    float a = acc + sc.part[tid];
                    __nv_bfloat16 hi = __float2bfloat16(a);
                    g_chi[bC * Hh + h] = hi;
                    g_clo[bC * Hh + h] = __float2bfloat16(a - __bfloat162float(hi));
                }
            }
        }
        gbar(bo);

        // ================= stage D: gx_ctx GEMM + fused gate update ===========
        if (g < 64) {
            SmemD& sd = *reinterpret_cast<SmemD*>(sraw);
            float c0[4] = {}, c1[4] = {}, c2[4] = {};

            auto issueD = [&](int st, int k0) {
                if (tid < 64) {
                    CPA16CG(smem_u32p(&sd.Ah[st][rA][cA]),     gAhD + k0);
                    CPA16CG(smem_u32p(&sd.Ah[st][rA][cA + 8]), gAhD + k0 + 8);
                } else if (tid < 128) {
                    CPA16CG(smem_u32p(&sd.Al[st][rA][cA]),     gAlD + k0);
                    CPA16CG(smem_u32p(&sd.Al[st][rA][cA + 8]), gAlD + k0 + 8);
                }
                if (tid < 192) {
                    CPA16(smem_u32p(&sd.Bh[st][lrB][lcB]),     gBhD + k0);
                    CPA16(smem_u32p(&sd.Bh[st][lrB][lcB + 8]), gBhD + k0 + 8);
                    CPA16(smem_u32p(&sd.Bl[st][lrB][lcB]),     gBlD + k0);
                    CPA16(smem_u32p(&sd.Bl[st][lrB][lcB + 8]), gBlD + k0 + 8);
                }
                CPA_COMMIT();
            };

            issueD(0, 0);
            issueD(1, 64);
            for (int k = 0; k < 16; k++) {
                const int st = k % 3;
                if (k < 14) { issueD((k + 2) % 3, (k + 2) * 64); CPA_WAIT(2); }
                else if (k == 14) CPA_WAIT(1);
                else CPA_WAIT(0);
                __syncthreads();
                if (tid < 192) {
#pragma unroll
                    for (int kk = 0; kk < 64; kk += 16) {
                        unsigned int ah0 = *(const unsigned int*)&sd.Ah[st][row][kk + kc];
                        unsigned int ah1 = *(const unsigned int*)&sd.Ah[st][row + 8][kk + kc];
                        unsigned int ah2 = *(const unsigned int*)&sd.Ah[st][row][kk + kc + 8];
                        unsigned int ah3 = *(const unsigned int*)&sd.Ah[st][row + 8][kk + kc + 8];
                        unsigned int al0 = *(const unsigned int*)&sd.Al[st][row][kk + kc];
                        unsigned int al1 = *(const unsigned int*)&sd.Al[st][row + 8][kk + kc];
                        unsigned int al2 = *(const unsigned int*)&sd.Al[st][row][kk + kc + 8];
                        unsigned int al3 = *(const unsigned int*)&sd.Al[st][row + 8][kk + kc + 8];
                        unsigned int bh0 = *(const unsigned int*)&sd.Bh[st][wn + row][kk + kc];
                        unsigned int bh1 = *(const unsigned int*)&sd.Bh[st][wn + row][kk + kc + 8];
                        unsigned int bl0 = *(const unsigned int*)&sd.Bl[st][wn + row][kk + kc];
                        unsigned int bl1 = *(const unsigned int*)&sd.Bl[st][wn + row][kk + kc + 8];
                        mma16816(c0, ah0, ah1, ah2, ah3, bh0, bh1);
                        mma16816(c1, ah0, ah1, ah2, ah3, bl0, bl1);
                        mma16816(c2, al0, al1, al2, al3, bh0, bh1);
                    }
                }
                __syncthreads();
            }
            if (tid < 192) {
                int gg = warp % 3, jgl = warp / 3;
                sd.sgx[jgl][gg][kc][row]         = c0[0] + c1[0] + c2[0];
                sd.sgx[jgl][gg][kc + 1][row]     = c0[1] + c1[1] + c2[1];
                sd.sgx[jgl][gg][kc][row + 8]     = c0[2] + c1[2] + c2[2];
                sd.sgx[jgl][gg][kc + 1][row + 8] = c0[3] + c1[3] + c2[3];
            }
            __syncthreads();
            {
                const float* hprev = g_H + (size_t)t * Bb * Hh;
                float* hnew = g_H + (size_t)(t + 1) * Bb * Hh;
                int m = tid & 15;
                int jloc = tid >> 4;
                int jgl = jloc >> 3, jl = jloc & 7;
                int j = (g & 63) * 16 + jloc;
                int r = t * Bb + m;
                const float* gxe = g_gxemb + (size_t)r * 3 * Hh;
                const float* g0 = g_gh2[0] + (size_t)m * 3 * Hh;
                const float* g1 = g_gh2[1] + (size_t)m * 3 * Hh;
                float gx_r = sd.sgx[jgl][0][jl][m] + gxe[j];
                float gx_z = sd.sgx[jgl][1][jl][m] + gxe[Hh + j];
                float gx_n = sd.sgx[jgl][2][jl][m] + gxe[2 * Hh + j];
                float gh_r = __ldcg(g0 + j)          + __ldcg(g1 + j)          + bhh[j];
                float gh_z = __ldcg(g0 + Hh + j)     + __ldcg(g1 + Hh + j)     + bhh[Hh + j];
                float gh_n = __ldcg(g0 + 2 * Hh + j) + __ldcg(g1 + 2 * Hh + j) + bhh[2 * Hh + j];
                float rg = fast_sigmoid(gx_r + gh_r);
                float z  = fast_sigmoid(gx_z + gh_z);
                float nn = fast_tanh(gx_n + rg * gh_n);
                float hp = hprev[m * Hh + j];
                float hv = (1.f - z) * nn + z * hp;
                hnew[m * Hh + j] = hv;
                g_Hbf[(size_t)r * Hh + j] = __float2bfloat16(hv);
                __nv_bfloat16 hi = __float2bfloat16(hv);
                g_hhi[m * Hh + j] = hi;
                g_hlo[m * Hh + j] = __float2bfloat16(hv - __bfloat162float(hi));
            }
        }
        gbar(bo);
    }
}

// -------- final: in-place log_softmax (2-pass: online logsumexp + subtract) --
__global__ __launch_bounds__(256) void logsoftmax_kernel(float* __restrict__ out)
{
    float* row = out + (size_t)blockIdx.x * Vv;
    int tid = threadIdx.x;
    __shared__ float smax[8], ssum[8];

    float m = -FLT_MAX, s = 0.f;
    for (int v = tid; v < Vv; v += 256) {
        float x = row[v];
        float mn = fmaxf(m, x);
        s = s * __expf(m - mn) + __expf(x - mn);
        m = mn;
    }
#pragma unroll
    for (int o = 16; o; o >>= 1) {
        float m2 = __shfl_xor_sync(~0u, m, o);
        float s2 = __shfl_xor_sync(~0u, s, o);
        float mn = fmaxf(m, m2);
        s = s * __expf(m - mn) + s2 * __expf(m2 - mn);
        m = mn;
    }
    if ((tid & 31) == 0) { smax[tid >> 5] = m; ssum[tid >> 5] = s; }
    __syncthreads();
    float M = smax[0];
#pragma unroll
    for (int i = 1; i < 8; i++) M = fmaxf(M, smax[i]);
    float S = 0.f;
#pragma unroll
    for (int i = 0; i < 8; i++) S += ssum[i] * __expf(smax[i] - M);

    float lse = M + logf(S);
    for (int v = tid; v < Vv; v += 256) row[v] -= lse;
}

// ---------------- orchestration ----------------
extern "C" void kernel_launch(void* const* d_in, const int* in_sizes, int n_in,
                              void* d_out, int out_size)
{
    const float* enc  = (const float*)d_in[0];
    const float* h0   = (const float*)d_in[1];
    const int*   tgt  = (const int*)  d_in[2];
    const float* emb  = (const float*)d_in[3];
    const float* Wq   = (const float*)d_in[4];
    const float* Wk   = (const float*)d_in[5];
    const float* vat  = (const float*)d_in[6];
    const float* Wih  = (const float*)d_in[7];
    const float* Whh  = (const float*)d_in[8];
    const float* bih  = (const float*)d_in[9];
    const float* bhh  = (const float*)d_in[10];
    const float* Wout = (const float*)d_in[11];
    const float* bout = (const float*)d_in[12];

    float* out       = (float*)d_out;
    float* out_hT    = out + (size_t)Bb * Tt * Vv;
    float* out_attw  = out_hT + (size_t)Bb * Hh;

    (void)in_sizes; (void)n_in; (void)out_size;

    cudaFuncSetAttribute(loop_kernel, cudaFuncAttributeMaxDynamicSharedMemorySize, LOOP_SMEM);

    // Phase 0: one-time conversions / precomputes
    conv_wout_kernel<<<4096, 256>>>(Wout);
    conv_wihemb_kernel<<<3 * Hh, 256>>>(Wih);
    conv_wcat_kernel<<<4 * Hh, 256>>>(Wq, Whh);
    conv_wc_kernel<<<3 * Hh, 256>>>(Wih);
    gather_emb_kernel<<<Tt * Bb, 256>>>(emb, tgt);
    {
        __nv_bfloat16 *Abf, *Bbf;
        float* gxemb_ptr;
        cudaGetSymbolAddress((void**)&Abf, g_embbf);
        cudaGetSymbolAddress((void**)&Bbf, g_Wihembbf);
        cudaGetSymbolAddress((void**)&gxemb_ptr, g_gxemb);
        bf16_mma_kernel<<<dim3(3 * Hh / 64, (Tt * Bb) / 128), 256>>>(
            Abf, Bbf, bih, gxemb_ptr, 3 * Hh, 0);
    }
    gemm_tn_kernel<<<dim3(Hh / 64, (Bb * Ss) / 64), 256>>>(enc, Wk, Hh);
    init_h_kernel<<<(Bb * Hh + 255) / 256, 256>>>(h0);

    // Phase 2: entire sequential decode in ONE persistent kernel
    loop_kernel<<<GRIDB, 256, LOOP_SMEM>>>(enc, vat, bhh, out_attw);

    copy_hT_kernel<<<(Bb * Hh + 255) / 256, 256>>>(out_hT);

    // Phase 3: logits on tensor cores + log_softmax
    {
        __nv_bfloat16 *Abf, *Bbf;
        cudaGetSymbolAddress((void**)&Abf, g_Hbf);
        cudaGetSymbolAddress((void**)&Bbf, g_Woutbf);
        bf16_mma_kernel<<<dim3(Vv / 64, (Tt * Bb) / 128), 256>>>(
            Abf, Bbf, bout, out, Vv, 1);
    }
    logsoftmax_kernel<<<Bb * Tt, 256>>>(out);
}